// round 3
// baseline (speedup 1.0000x reference)
#include <cuda_runtime.h>

// ---------------- problem constants ----------------
#define NBLK   6
#define DF     45          // features
#define HID    256         // hidden width
#define LHID   2           // hidden layers per block
#define MPAR   23          // params per feature (3K-1, K=8)
#define DM     (DF*MPAR)   // 1035
#define ROWS   64          // batch rows per CTA
#define NTHR   512
#define FPG    9           // features per spline group (45 = 5*9)
#define PCOLS  (FPG*MPAR)  // 207
#define FGCNT  5
#define K0PAD  48          // layer-0 K padded (45 feat + cond + 2 zero)

typedef unsigned long long ull;

__device__ __forceinline__ ull pack2(float x, float y) {
    ull r; asm("mov.b64 %0, {%1,%2};" : "=l"(r) : "f"(x), "f"(y)); return r;
}
__device__ __forceinline__ void ffma2(ull& d, ull a, ull b) {
    asm("fma.rn.f32x2 %0, %1, %2, %3;" : "=l"(d) : "l"(a), "l"(b), "l"(d));
}

// ---------------- scratch (masked / transposed weights) ----------------
__device__ float g_W0t[NBLK * K0PAD * HID];            // [b][k][h]
__device__ float g_b0c[NBLK * HID];
__device__ float g_Wht[NBLK * LHID * HID * HID];       // [b][l][k][o]
__device__ float g_Wft[NBLK * FGCNT * HID * 256];      // [b][fg][k][256] (207 used, padded)

// ---------------- prep kernels (apply MADE masks, transpose) ----------------
__global__ void prep_w0(const float* __restrict__ W0, const float* __restrict__ Wc,
                        const float* __restrict__ b0, const float* __restrict__ bc) {
    int idx = blockIdx.x * blockDim.x + threadIdx.x;
    const int total = NBLK * K0PAD * HID;
    if (idx < total) {
        int b = idx / (K0PAD * HID);
        int rem = idx % (K0PAD * HID);
        int k = rem / HID;
        int h = rem % HID;
        float v = 0.0f;
        if (k < DF) {                 // m0[h][d] = (h%44 >= d)
            v = ((h % 44) >= k) ? W0[(b * HID + h) * DF + k] : 0.0f;
        } else if (k == DF) {         // cond weight (unmasked)
            v = Wc[b * HID + h];
        }
        g_W0t[idx] = v;
    }
    if (idx < NBLK * HID) g_b0c[idx] = b0[idx] + bc[idx];
}

__global__ void prep_wh(const float* __restrict__ Wh) {
    int idx = blockIdx.x * blockDim.x + threadIdx.x;
    const int total = NBLK * LHID * HID * HID;
    if (idx >= total) return;
    int bl = idx >> 16;
    int k  = (idx >> 8) & 255;
    int o  = idx & 255;
    // mh[o][k] = (o%44 >= k%44)
    float v = ((o % 44) >= (k % 44)) ? Wh[(bl * HID + o) * HID + k] : 0.0f;
    g_Wht[idx] = v;
}

__global__ void prep_wf(const float* __restrict__ Wf) {
    int idx = blockIdx.x * blockDim.x + threadIdx.x;
    const int total = NBLK * FGCNT * HID * 256;
    if (idx >= total) return;
    int b   = idx / (FGCNT * HID * 256);
    int rem = idx % (FGCNT * HID * 256);
    int fg  = rem / (HID * 256);
    int rem2 = rem % (HID * 256);
    int k = rem2 / 256;
    int c = rem2 % 256;
    float v = 0.0f;
    if (c < PCOLS) {
        int o = fg * PCOLS + c;         // global output column
        int f = o / MPAR;               // feature index
        // mf[o][k] = (f > k%44)
        if (f > (k % 44)) v = Wf[(b * DM + o) * HID + k];
    }
    g_Wft[idx] = v;
}

// ---------------- fused GEMM tile via packed f32x2 FMA ----------------
// src2: smem float2 [32 pair-rows][SSTR2]; dst2: smem float2 [32][256]
// Wt: global [K][256] (masked/padded); 512 threads: 8 row-groups x 64 col-lanes.
template<int K, int NCOLS, bool RELU, int SSTR2>
__device__ __forceinline__ void gemm2(const float* __restrict__ Wt,
                                      const float* __restrict__ bias,
                                      const float2* __restrict__ src2,
                                      float2* __restrict__ dst2,
                                      float* __restrict__ Wsm, int tid)
{
    const int rg = tid >> 6;       // 0..7 (8 rows = 4 row-pairs each)
    const int c0 = tid & 63;       // column base; cols c0 + 64*j
    ull acc[4][4];
    #pragma unroll
    for (int j = 0; j < 4; j++) {
        int c = c0 + 64 * j;
        float bv = (c < NCOLS) ? bias[c] : 0.0f;
        ull bp = pack2(bv, bv);
        #pragma unroll
        for (int p = 0; p < 4; p++) acc[p][j] = bp;
    }
    const float2* srcb = src2 + (rg * 4) * SSTR2;
    const int skk = tid >> 6;      // staging row 0..7
    const int scc = tid & 63;      // staging float4 col 0..63

    #pragma unroll 1
    for (int k0 = 0; k0 < K; k0 += 16) {
        __syncthreads();
        // stage 16 x 256 weight slab: 2 x (LDG.128 + STS.128) per thread
        ((float4*)(Wsm + skk * 256))[scc]       = ((const float4*)(Wt + (k0 + skk) * 256))[scc];
        ((float4*)(Wsm + (skk + 8) * 256))[scc] = ((const float4*)(Wt + (k0 + skk + 8) * 256))[scc];
        __syncthreads();
        #pragma unroll
        for (int kk = 0; kk < 16; kk++) {
            ull a[4];
            #pragma unroll
            for (int p = 0; p < 4; p++)
                a[p] = *(const ull*)(srcb + p * SSTR2 + (k0 + kk));   // LDS.64 broadcast
            #pragma unroll
            for (int j = 0; j < 4; j++) {
                float w = Wsm[kk * 256 + c0 + 64 * j];                // conflict-free LDS
                ull w2 = pack2(w, w);
                #pragma unroll
                for (int p = 0; p < 4; p++) ffma2(acc[p][j], a[p], w2);
            }
        }
    }
    #pragma unroll
    for (int j = 0; j < 4; j++) {
        int c = c0 + 64 * j;
        if (c < NCOLS) {
            #pragma unroll
            for (int p = 0; p < 4; p++) {
                float2 v = *(float2*)&acc[p][j];
                if (RELU) { v.x = fmaxf(v.x, 0.0f); v.y = fmaxf(v.y, 0.0f); }
                dst2[(rg * 4 + p) * 256 + c] = v;
            }
        }
    }
    __syncthreads();
}

// ---------------- rational-quadratic spline (tails='linear'), K=8 bins ----------------
// p: strided float pointer (stride 2: params live in one half of a float2 array)
__device__ __forceinline__ float2 rq_spline(const float* __restrict__ p, float x)
{
    const float TAIL = 13.815510557964274f;   // -log(1e-6)
    const float INVS = 0.0625f;               // 1/sqrt(256)
    bool inside = (x >= -TAIL) && (x <= TAIL);
    float xc = fminf(fmaxf(x, -TAIL), TAIL);

    float ew[8], eh[8];
    float mw = -1e30f, mhh = -1e30f;
    #pragma unroll
    for (int i = 0; i < 8; i++) {
        float a = p[2 * i] * INVS, b = p[2 * (8 + i)] * INVS;
        ew[i] = a; eh[i] = b;
        mw = fmaxf(mw, a); mhh = fmaxf(mhh, b);
    }
    float sw = 0.0f, sh = 0.0f;
    #pragma unroll
    for (int i = 0; i < 8; i++) {
        ew[i] = __expf(ew[i] - mw);  sw += ew[i];
        eh[i] = __expf(eh[i] - mhh); sh += eh[i];
    }
    float iw = 1.0f / sw, ihs = 1.0f / sh;

    float d[9];
    d[0] = 1.0f; d[8] = 1.0f;                 // MIN_D + softplus(const) == 1 exactly
    #pragma unroll
    for (int i = 0; i < 7; i++) {
        float u = p[2 * (16 + i)];
        d[i + 1] = 1e-3f + fmaxf(u, 0.0f) + log1pf(__expf(-fabsf(u)));
    }

    float cumw = 0.0f, cumh = 0.0f;
    float cwl = -TAIL, chl = -TAIL;
    float bcwl = -TAIL, bw = 1.0f, bchl = -TAIL, bh2 = 1.0f, bd0 = 1.0f, bd1 = 1.0f;
    #pragma unroll
    for (int i = 0; i < 8; i++) {
        cumw += 1e-3f + 0.992f * (ew[i] * iw);
        cumh += 1e-3f + 0.992f * (eh[i] * ihs);
        float cwr = (i == 7) ? TAIL : fmaf(2.0f * TAIL, cumw, -TAIL);
        float chr = (i == 7) ? TAIL : fmaf(2.0f * TAIL, cumh, -TAIL);
        bool sel = (xc >= cwl);
        if (sel) { bcwl = cwl; bw = cwr - cwl; bchl = chl; bh2 = chr - chl; bd0 = d[i]; bd1 = d[i + 1]; }
        cwl = cwr; chl = chr;
    }

    float th    = (xc - bcwl) / bw;
    float th1   = th * (1.0f - th);
    float delta = bh2 / bw;
    float den   = delta + (bd0 + bd1 - 2.0f * delta) * th1;
    float y     = bchl + bh2 * (delta * th * th + bd0 * th1) / den;
    float omt   = 1.0f - th;
    float lnum  = delta * delta * (bd1 * th * th + 2.0f * delta * th1 + bd0 * omt * omt);
    float lad   = __logf(lnum) - 2.0f * __logf(den);

    float2 r;
    r.x = inside ? y : x;
    r.y = inside ? lad : 0.0f;
    return r;
}

// ---------------- main fused kernel ----------------
// smem (floats): z2 32x48x2 = 3072, hidA2 32x256x2 = 16384, hidB2 16384, Wsm 4096, ld 64
#define SMEM_FLOATS (3072 + 16384 + 16384 + 4096 + 64)
#define SMEM_BYTES  (SMEM_FLOATS * 4)

__global__ __launch_bounds__(NTHR, 1)
void maf_kernel(const float* __restrict__ x, const float* __restrict__ cond,
                const float* __restrict__ bh, const float* __restrict__ bf,
                float* __restrict__ out)
{
    extern __shared__ float sm[];
    float2* z2    = (float2*)sm;            // [32 pair-rows][48]
    float2* hidA2 = z2 + 32 * 48;           // [32][256]
    float2* hidB2 = hidA2 + 32 * 256;       // [32][256], also params buffer
    float*  Wsm   = (float*)(hidB2 + 32 * 256);  // [16][256]
    float*  ld_s  = Wsm + 16 * 256;         // [64]

    const int tid  = threadIdx.x;
    const int row0 = blockIdx.x * ROWS;
    float* zf = (float*)z2;   // element (r,f) at (((r>>1)*48+f)<<1) | (r&1)

    for (int idx = tid; idx < ROWS * DF; idx += NTHR) {
        int r = idx / DF, f = idx - r * DF;
        zf[((((r >> 1) * 48) + f) << 1) | (r & 1)] = x[(row0 + r) * DF + f];
    }
    if (tid < ROWS) {
        int r = tid;
        zf[((((r >> 1) * 48) + 45) << 1) | (r & 1)] = cond[row0 + r];
        zf[((((r >> 1) * 48) + 46) << 1) | (r & 1)] = 0.0f;
        zf[((((r >> 1) * 48) + 47) << 1) | (r & 1)] = 0.0f;
        ld_s[r] = 0.0f;
    }
    // first gemm's internal barrier orders these writes before any read

    for (int b = 0; b < NBLK; b++) {
        // layer 0 (z + cond -> hid), no relu
        gemm2<K0PAD, 256, false, 48>(
            g_W0t + b * K0PAD * HID, g_b0c + b * HID, z2, hidA2, Wsm, tid);
        // hidden layers with relu
        gemm2<256, 256, true, 256>(
            g_Wht + (b * 2 + 0) * HID * HID, bh + (b * 2 + 0) * HID, hidA2, hidB2, Wsm, tid);
        gemm2<256, 256, true, 256>(
            g_Wht + (b * 2 + 1) * HID * HID, bh + (b * 2 + 1) * HID, hidB2, hidA2, Wsm, tid);
        // output layer + spline, 5 feature groups of 9 features
        for (int fg = 0; fg < FGCNT; fg++) {
            gemm2<256, PCOLS, false, 256>(
                g_Wft + (b * FGCNT + fg) * HID * 256, bf + b * DM + fg * PCOLS,
                hidA2, hidB2, Wsm, tid);
            const float* pb = (const float*)hidB2;
            for (int t = tid; t < ROWS * FPG; t += NTHR) {
                int r  = t & 63;
                int fl = t >> 6;
                int f  = fg * FPG + fl;
                float xv = zf[((((r >> 1) * 48) + f) << 1) | (r & 1)];
                const float* p = pb + ((((r >> 1) * 256) + fl * MPAR) << 1) + (r & 1);
                float2 yr = rq_spline(p, xv);
                zf[((((r >> 1) * 48) + f) << 1) | (r & 1)] = yr.x;
                atomicAdd(&ld_s[r], yr.y);
            }
            __syncthreads();
        }
    }
    __syncthreads();
    if (tid < ROWS) {
        int r = tid;
        float s = 0.0f;
        #pragma unroll
        for (int f = 0; f < DF; f++) {
            float v = zf[((((r >> 1) * 48) + f) << 1) | (r & 1)];
            s = fmaf(v, v, s);
        }
        out[row0 + r] = -0.5f * s - 41.35223399420827f + ld_s[r];
    }
}

// ---------------- launch ----------------
extern "C" void kernel_launch(void* const* d_in, const int* in_sizes, int n_in,
                              void* d_out, int out_size) {
    const float* x    = (const float*)d_in[0];
    const float* cond = (const float*)d_in[1];
    const float* W0   = (const float*)d_in[2];
    const float* b0   = (const float*)d_in[3];
    const float* Wc   = (const float*)d_in[4];
    const float* bc   = (const float*)d_in[5];
    const float* Wh   = (const float*)d_in[6];
    const float* bh   = (const float*)d_in[7];
    const float* Wf   = (const float*)d_in[8];
    const float* bf   = (const float*)d_in[9];
    float* out = (float*)d_out;
    const int B = in_sizes[0] / DF;

    prep_w0<<<(NBLK * K0PAD * HID + 255) / 256, 256>>>(W0, Wc, b0, bc);
    prep_wh<<<(NBLK * LHID * HID * HID + 255) / 256, 256>>>(Wh);
    prep_wf<<<(NBLK * FGCNT * HID * 256 + 255) / 256, 256>>>(Wf);

    cudaFuncSetAttribute(maf_kernel, cudaFuncAttributeMaxDynamicSharedMemorySize, SMEM_BYTES);
    maf_kernel<<<B / ROWS, NTHR, SMEM_BYTES>>>(x, cond, bh, bf, out);
}

// round 6
// speedup vs baseline: 4.4650x; 4.4650x over previous
#include <cuda_runtime.h>

// ---------------- problem constants ----------------
#define NBLK 6
#define DF   45
#define DM   1035
#define MROWS 128
#define NTHR 512
#define K0   48            // layer-0 K (45 z + cond + 1.0 + zero)
#define ASTR 260           // act row stride (floats) - conflict-free fragments
#define ZS   52            // z row stride
#define WSTR 260           // hidden weight slab stride
#define FWSTR 56           // f-layer weight slab stride
#define PSTR 56            // params buffer stride
#define NCH  23            // output-layer chunks (2 features each)
#define FCOLS 48           // padded cols per chunk (2 x 24)

// smem map (floats)
#define OFF_Z   0
#define OFF_LD  (128*ZS)                 // 6656
#define OFF_ACT (OFF_LD + 128)           // 6784
#define OFF_REG (OFF_ACT + 128*ASTR)     // 40064
#define OFF_PAR (OFF_REG + 2*32*FWSTR)   // 43648
#define SMEM_FLOATS (OFF_REG + 2*32*WSTR)  // 56704
#define SMEM_BYTES  (SMEM_FLOATS * 4)      // 226816

// ---------------- device weight images (masked, k-major) ----------------
__device__ float g_W0[NBLK * K0 * 256];            // [b][k48][n256]
__device__ float g_Wh[NBLK * 2 * 256 * 256];       // [b*2+l][k][n]
__device__ float g_Wf[NBLK * NCH * 256 * FCOLS];   // [b][ch][k][48]

// ---------------- helpers ----------------
__device__ __forceinline__ unsigned smem_u32(const void* p) {
    unsigned a; asm("{ .reg .u64 t; cvta.to.shared.u64 t, %1; cvt.u32.u64 %0, t; }" : "=r"(a) : "l"(p));
    return a;
}
__device__ __forceinline__ void cpa16(unsigned d, const float* s) {
    asm volatile("cp.async.ca.shared.global [%0], [%1], 16;" :: "r"(d), "l"(s));
}
__device__ __forceinline__ void mma8(float* d, const unsigned* a, unsigned b0, unsigned b1) {
    asm volatile("mma.sync.aligned.m16n8k8.row.col.f32.tf32.tf32.f32 "
        "{%0,%1,%2,%3},{%4,%5,%6,%7},{%8,%9},{%0,%1,%2,%3};"
        : "+f"(d[0]), "+f"(d[1]), "+f"(d[2]), "+f"(d[3])
        : "r"(a[0]), "r"(a[1]), "r"(a[2]), "r"(a[3]), "r"(b0), "r"(b1));
}

template<int NF4, int ROWF4, int WS>
__device__ __forceinline__ void stage_w(unsigned dst_sm, const float* __restrict__ src, int tid) {
    for (int i = tid; i < NF4; i += NTHR) {
        int k = i / ROWF4, c = i - k * ROWF4;
        cpa16(dst_sm + (unsigned)((k * WS + c * 4) * 4), src + (size_t)k * (ROWF4 * 4) + c * 4);
    }
    asm volatile("cp.async.commit_group;" ::: "memory");
}

// ---------------- prep kernels (mask + transpose to k-major) ----------------
__global__ void prep_w0(const float* __restrict__ W0, const float* __restrict__ Wc,
                        const float* __restrict__ b0, const float* __restrict__ bc) {
    int idx = blockIdx.x * blockDim.x + threadIdx.x;
    if (idx >= NBLK * K0 * 256) return;
    int n = idx & 255, k = (idx >> 8) % K0, b = idx / (K0 * 256);
    float v = 0.0f;
    if (k < DF)       v = ((n % 44) >= k) ? W0[(b * 256 + n) * DF + k] : 0.0f;
    else if (k == 45) v = Wc[b * 256 + n];
    else if (k == 46) v = b0[b * 256 + n] + bc[b * 256 + n];
    g_W0[idx] = v;
}
__global__ void prep_wh(const float* __restrict__ Wh) {
    int idx = blockIdx.x * blockDim.x + threadIdx.x;
    if (idx >= NBLK * 2 * 256 * 256) return;
    int n = idx & 255, k = (idx >> 8) & 255, bl = idx >> 16;
    g_Wh[idx] = ((n % 44) >= (k % 44)) ? Wh[(bl * 256 + n) * 256 + k] : 0.0f;
}
__global__ void prep_wf(const float* __restrict__ Wf) {
    int idx = blockIdx.x * blockDim.x + threadIdx.x;
    if (idx >= NBLK * NCH * 256 * FCOLS) return;
    int c = idx % FCOLS;
    int k = (idx / FCOLS) & 255;
    int ch = (idx / (FCOLS * 256)) % NCH;
    int b = idx / (FCOLS * 256 * NCH);
    int fl = c / 24, i = c % 24;
    int f = ch * 2 + fl;
    float v = 0.0f;
    if (i < 23 && f < DF && f > (k % 44))
        v = Wf[((size_t)(b * DM + f * 23 + i)) * 256 + k];
    g_Wf[idx] = v;
}

// ---------------- dense layer: [128 x 256] = A[128 x K] * W[K x 256] ----------------
// warp grid 4M x 4N, warp tile 32x64; in-place on act is safe (write after barrier)
template<int NSLAB, int KSLAB, bool BR>
__device__ __forceinline__ void dense_layer(const float* __restrict__ Wg,
                                            const float* __restrict__ bias,
                                            const float* As, int astr,
                                            float* act, float* wreg, unsigned wreg_sm, int tid)
{
    const int lane = tid & 31, w = tid >> 5;
    const int wm = w & 3, wn = w >> 2;
    const int g = lane >> 2, t = lane & 3;
    constexpr int NF4 = KSLAB * 64;

    float acc[2][8][4];
    #pragma unroll
    for (int mt = 0; mt < 2; mt++)
        #pragma unroll
        for (int nt = 0; nt < 8; nt++)
            acc[mt][nt][0] = acc[mt][nt][1] = acc[mt][nt][2] = acc[mt][nt][3] = 0.0f;

    stage_w<NF4, 64, WSTR>(wreg_sm, Wg, tid);
    if (NSLAB > 1) stage_w<NF4, 64, WSTR>(wreg_sm + KSLAB * WSTR * 4, Wg + KSLAB * 256, tid);

    for (int s = 0; s < NSLAB; s++) {
        if (s < NSLAB - 1) asm volatile("cp.async.wait_group 1;" ::: "memory");
        else               asm volatile("cp.async.wait_group 0;" ::: "memory");
        __syncthreads();
        const float* Ws = wreg + (s & 1) * KSLAB * WSTR;
        #pragma unroll
        for (int k8 = 0; k8 < KSLAB / 8; k8++) {
            const int kg = s * KSLAB + k8 * 8;
            unsigned a[2][4];
            #pragma unroll
            for (int mt = 0; mt < 2; mt++) {
                int r0 = wm * 32 + mt * 16 + g;
                a[mt][0] = __float_as_uint(As[r0 * astr + kg + t]);
                a[mt][1] = __float_as_uint(As[(r0 + 8) * astr + kg + t]);
                a[mt][2] = __float_as_uint(As[r0 * astr + kg + t + 4]);
                a[mt][3] = __float_as_uint(As[(r0 + 8) * astr + kg + t + 4]);
            }
            #pragma unroll
            for (int nt = 0; nt < 8; nt++) {
                int col = wn * 64 + nt * 8 + g;
                unsigned b0 = __float_as_uint(Ws[(k8 * 8 + t) * WSTR + col]);
                unsigned b1 = __float_as_uint(Ws[(k8 * 8 + t + 4) * WSTR + col]);
                mma8(acc[0][nt], a[0], b0, b1);
                mma8(acc[1][nt], a[1], b0, b1);
            }
        }
        __syncthreads();
        if (s + 2 < NSLAB)
            stage_w<NF4, 64, WSTR>(wreg_sm + (s & 1) * KSLAB * WSTR * 4,
                                   Wg + (size_t)(s + 2) * KSLAB * 256, tid);
    }
    // epilogue (all reads done at loop's trailing barrier)
    #pragma unroll
    for (int mt = 0; mt < 2; mt++)
        #pragma unroll
        for (int nt = 0; nt < 8; nt++) {
            int r0 = wm * 32 + mt * 16 + g;
            int col = wn * 64 + nt * 8 + 2 * t;
            float bx = 0.0f, by = 0.0f;
            if (BR) { float2 bb = *(const float2*)(bias + col); bx = bb.x; by = bb.y; }
            float v0 = acc[mt][nt][0] + bx, v1 = acc[mt][nt][1] + by;
            float v2 = acc[mt][nt][2] + bx, v3 = acc[mt][nt][3] + by;
            if (BR) {
                v0 = fmaxf(v0, 0.0f); v1 = fmaxf(v1, 0.0f);
                v2 = fmaxf(v2, 0.0f); v3 = fmaxf(v3, 0.0f);
            }
            *(float2*)&act[r0 * ASTR + col]       = make_float2(v0, v1);
            *(float2*)&act[(r0 + 8) * ASTR + col] = make_float2(v2, v3);
        }
    __syncthreads();
}

// ---------------- output-layer chunk: [128 x 48] = act[128 x 256] * Wf[256 x 48] ----------------
// warp grid 8M x 2N, warp tile 16x24
__device__ __forceinline__ void f_layer(const float* __restrict__ Wg,
                                        const float* act, float* par,
                                        float* wreg, unsigned wreg_sm, int tid)
{
    const int lane = tid & 31, w = tid >> 5;
    const int wm = w & 7, wn = w >> 3;
    const int g = lane >> 2, t = lane & 3;
    float acc[3][4];
    #pragma unroll
    for (int nt = 0; nt < 3; nt++)
        acc[nt][0] = acc[nt][1] = acc[nt][2] = acc[nt][3] = 0.0f;

    stage_w<384, 12, FWSTR>(wreg_sm, Wg, tid);
    stage_w<384, 12, FWSTR>(wreg_sm + 32 * FWSTR * 4, Wg + 32 * FCOLS, tid);

    for (int s = 0; s < 8; s++) {
        if (s < 7) asm volatile("cp.async.wait_group 1;" ::: "memory");
        else       asm volatile("cp.async.wait_group 0;" ::: "memory");
        __syncthreads();
        const float* Ws = wreg + (s & 1) * 32 * FWSTR;
        #pragma unroll
        for (int k8 = 0; k8 < 4; k8++) {
            const int kg = s * 32 + k8 * 8;
            const int r0 = wm * 16 + g;
            unsigned a[4];
            a[0] = __float_as_uint(act[r0 * ASTR + kg + t]);
            a[1] = __float_as_uint(act[(r0 + 8) * ASTR + kg + t]);
            a[2] = __float_as_uint(act[r0 * ASTR + kg + t + 4]);
            a[3] = __float_as_uint(act[(r0 + 8) * ASTR + kg + t + 4]);
            #pragma unroll
            for (int nt = 0; nt < 3; nt++) {
                int col = wn * 24 + nt * 8 + g;
                unsigned b0 = __float_as_uint(Ws[(k8 * 8 + t) * FWSTR + col]);
                unsigned b1 = __float_as_uint(Ws[(k8 * 8 + t + 4) * FWSTR + col]);
                mma8(acc[nt], a, b0, b1);
            }
        }
        __syncthreads();
        if (s + 2 < 8)
            stage_w<384, 12, FWSTR>(wreg_sm + (s & 1) * 32 * FWSTR * 4,
                                    Wg + (size_t)(s + 2) * 32 * FCOLS, tid);
    }
    #pragma unroll
    for (int nt = 0; nt < 3; nt++) {
        int r0 = wm * 16 + g;
        int col = wn * 24 + nt * 8 + 2 * t;
        *(float2*)&par[r0 * PSTR + col]       = make_float2(acc[nt][0], acc[nt][1]);
        *(float2*)&par[(r0 + 8) * PSTR + col] = make_float2(acc[nt][2], acc[nt][3]);
    }
    __syncthreads();
}

// ---------------- rational-quadratic spline, K=8 bins ----------------
__device__ __forceinline__ float2 rq_spline(const float* __restrict__ p, float x)
{
    const float TAIL = 13.815510557964274f;
    const float INVS = 0.0625f;
    bool inside = (x >= -TAIL) && (x <= TAIL);
    float xc = fminf(fmaxf(x, -TAIL), TAIL);

    float ew[8], eh[8], mw = -1e30f, mh = -1e30f;
    #pragma unroll
    for (int i = 0; i < 8; i++) {
        float a = p[i] * INVS, bb = p[8 + i] * INVS;
        ew[i] = a; eh[i] = bb;
        mw = fmaxf(mw, a); mh = fmaxf(mh, bb);
    }
    float sw = 0.0f, sh = 0.0f;
    #pragma unroll
    for (int i = 0; i < 8; i++) {
        ew[i] = __expf(ew[i] - mw);  sw += ew[i];
        eh[i] = __expf(eh[i] - mh);  sh += eh[i];
    }
    float iw = 1.0f / sw, ih = 1.0f / sh;

    float d[9]; d[0] = 1.0f; d[8] = 1.0f;
    #pragma unroll
    for (int i = 0; i < 7; i++) {
        float u = p[16 + i];
        d[i + 1] = 1e-3f + fmaxf(u, 0.0f) + log1pf(__expf(-fabsf(u)));
    }

    float cumw = 0.0f, cumh = 0.0f, cwl = -TAIL, chl = -TAIL;
    float bcwl = -TAIL, bw = 1.0f, bchl = -TAIL, bh2 = 1.0f, bd0 = 1.0f, bd1 = 1.0f;
    #pragma unroll
    for (int i = 0; i < 8; i++) {
        cumw += 1e-3f + 0.992f * (ew[i] * iw);
        cumh += 1e-3f + 0.992f * (eh[i] * ih);
        float cwr = (i == 7) ? TAIL : fmaf(2.0f * TAIL, cumw, -TAIL);
        float chr = (i == 7) ? TAIL : fmaf(2.0f * TAIL, cumh, -TAIL);
        if (xc >= cwl) { bcwl = cwl; bw = cwr - cwl; bchl = chl; bh2 = chr - chl; bd0 = d[i]; bd1 = d[i + 1]; }
        cwl = cwr; chl = chr;
    }

    float th  = (xc - bcwl) / bw;
    float th1 = th * (1.0f - th);
    float dl  = bh2 / bw;
    float den = dl + (bd0 + bd1 - 2.0f * dl) * th1;
    float y   = bchl + bh2 * (dl * th * th + bd0 * th1) / den;
    float omt = 1.0f - th;
    float ln  = dl * dl * (bd1 * th * th + 2.0f * dl * th1 + bd0 * omt * omt);
    float lad = __logf(ln) - 2.0f * __logf(den);
    float2 r; r.x = inside ? y : x; r.y = inside ? lad : 0.0f;
    return r;
}

// ---------------- main fused kernel ----------------
__global__ void __launch_bounds__(NTHR, 1)
maf_kernel(const float* __restrict__ x, const float* __restrict__ cond,
           const float* __restrict__ bh, const float* __restrict__ bf,
           float* __restrict__ out)
{
    extern __shared__ float sm[];
    float* z_s  = sm + OFF_Z;      // [128][52]
    float* ld_s = sm + OFF_LD;     // [128]
    float* act  = sm + OFF_ACT;    // [128][260]
    float* wreg = sm + OFF_REG;    // weight slabs / params region
    float* par  = sm + OFF_PAR;    // [128][56]
    const unsigned wreg_sm = smem_u32(wreg);

    const int tid  = threadIdx.x;
    const int row0 = blockIdx.x * MROWS;

    for (int i = tid; i < MROWS * DF; i += NTHR) {
        int r = i / DF, f = i - r * DF;
        z_s[r * ZS + f] = x[(row0 + r) * DF + f];
    }
    if (tid < MROWS) {
        z_s[tid * ZS + 45] = cond[row0 + tid];
        z_s[tid * ZS + 46] = 1.0f;            // bias lane for layer 0
        #pragma unroll
        for (int c = 47; c < ZS; c++) z_s[tid * ZS + c] = 0.0f;
        ld_s[tid] = 0.0f;
    }
    __syncthreads();

    for (int b = 0; b < NBLK; b++) {
        dense_layer<1, K0, false>(g_W0 + b * K0 * 256, nullptr,
                                  z_s, ZS, act, wreg, wreg_sm, tid);
        dense_layer<8, 32, true>(g_Wh + (size_t)(b * 2 + 0) * 65536, bh + (b * 2 + 0) * 256,
                                 act, ASTR, act, wreg, wreg_sm, tid);
        dense_layer<8, 32, true>(g_Wh + (size_t)(b * 2 + 1) * 65536, bh + (b * 2 + 1) * 256,
                                 act, ASTR, act, wreg, wreg_sm, tid);

        for (int ch = 0; ch < NCH; ch++) {
            f_layer(g_Wf + (size_t)(b * NCH + ch) * 256 * FCOLS, act, par, wreg, wreg_sm, tid);
            if (tid < 256) {
                int r = tid >> 1, fl = tid & 1, f = ch * 2 + fl;
                float lsum = 0.0f;
                if (f < DF) {
                    const float* bfp = bf + b * DM + f * 23;
                    float p[23];
                    #pragma unroll
                    for (int i = 0; i < 23; i++)
                        p[i] = par[r * PSTR + fl * 24 + i] + bfp[i];
                    float xv = z_s[r * ZS + f];
                    float2 yr = rq_spline(p, xv);
                    z_s[r * ZS + f] = yr.x;
                    lsum = yr.y;
                }
                float tot = lsum + __shfl_xor_sync(0xffffffff, lsum, 1);
                if (!(tid & 1)) ld_s[r] += tot;
            }
            __syncthreads();
        }
    }

    if (tid < MROWS) {
        float s = 0.0f;
        #pragma unroll
        for (int f = 0; f < DF; f++) { float v = z_s[tid * ZS + f]; s = fmaf(v, v, s); }
        out[row0 + tid] = -0.5f * s - 41.35223399420827f + ld_s[tid];
    }
}

// ---------------- launch ----------------
extern "C" void kernel_launch(void* const* d_in, const int* in_sizes, int n_in,
                              void* d_out, int out_size) {
    const float* x    = (const float*)d_in[0];
    const float* cond = (const float*)d_in[1];
    const float* W0   = (const float*)d_in[2];
    const float* b0   = (const float*)d_in[3];
    const float* Wc   = (const float*)d_in[4];
    const float* bc   = (const float*)d_in[5];
    const float* Wh   = (const float*)d_in[6];
    const float* bh   = (const float*)d_in[7];
    const float* Wf   = (const float*)d_in[8];
    const float* bf   = (const float*)d_in[9];
    float* out = (float*)d_out;
    const int B = in_sizes[0] / DF;

    prep_w0<<<(NBLK * K0 * 256 + 255) / 256, 256>>>(W0, Wc, b0, bc);
    prep_wh<<<(NBLK * 2 * 256 * 256 + 255) / 256, 256>>>(Wh);
    prep_wf<<<(NBLK * NCH * 256 * FCOLS + 255) / 256, 256>>>(Wf);

    cudaFuncSetAttribute(maf_kernel, cudaFuncAttributeMaxDynamicSharedMemorySize, SMEM_BYTES);
    maf_kernel<<<B / MROWS, NTHR, SMEM_BYTES>>>(x, cond, bh, bf, out);
}

// round 7
// speedup vs baseline: 6.3888x; 1.4308x over previous
#include <cuda_runtime.h>
#include <cuda_fp16.h>

// ---------------- problem constants ----------------
#define NBLK 6
#define DF   45
#define DM   1035
#define MROWS 128
#define NTHR 512

#define Z32S 49            // fp32 z row stride
#define Z16S 72            // fp16 z row stride (halves), 64 cols (2 k-slabs)
#define AS16 264           // fp16 act row stride (halves), 256 cols (8 k-slabs)
#define WPAD 40            // halves per k-slab row (32 data + 8 pad)
#define PSTR 98            // fp32 params row stride
#define FN   96            // f-chunk cols (4 features x 24)
#define NCHK 12            // f chunks

// smem byte offsets
#define OB_Z32 0
#define OB_Z16 25088                  // 128*49*4
#define OB_LD  (OB_Z16 + 18432)       // 128*72*2
#define OB_ACT (OB_LD + 512)
#define OB_WRG (OB_ACT + 67584)       // 128*264*2
#define OB_PAR (OB_WRG + 15360)       // after f wreg (2*96*40*2); overlaps hidden wreg (dead then)
#define SMEM_BYTES (OB_PAR + 50176)   // 128*98*4  -> 177152 total

// ---------------- device weight images (masked, slab-blocked, interleaved, fp16) ----------------
__device__ __half g_W0h[NBLK * 2 * 256 * WPAD];
__device__ __half g_Whh[NBLK * 2 * 8 * 256 * WPAD];
__device__ __half g_Wfh[NBLK * NCHK * 8 * FN * WPAD];

// ---------------- helpers ----------------
__device__ __forceinline__ unsigned smem_u32(const void* p) {
    unsigned a; asm("{ .reg .u64 t; cvta.to.shared.u64 t, %1; cvt.u32.u64 %0, t; }" : "=r"(a) : "l"(p));
    return a;
}
__device__ __forceinline__ void cpa16(unsigned d, const void* s) {
    asm volatile("cp.async.ca.shared.global [%0], [%1], 16;" :: "r"(d), "l"(s));
}
__device__ __forceinline__ void mma16(float* d, unsigned a0, unsigned a1, unsigned a2, unsigned a3,
                                      unsigned b0, unsigned b1) {
    asm volatile("mma.sync.aligned.m16n8k16.row.col.f32.f16.f16.f32 "
        "{%0,%1,%2,%3},{%4,%5,%6,%7},{%8,%9},{%0,%1,%2,%3};"
        : "+f"(d[0]), "+f"(d[1]), "+f"(d[2]), "+f"(d[3])
        : "r"(a0), "r"(a1), "r"(a2), "r"(a3), "r"(b0), "r"(b1));
}
// phys column of logical k within interleaved 32-k slabs
__device__ __forceinline__ int acol(int c) {
    int s = c >> 5, k32 = c & 31, step = k32 >> 4, w16 = k32 & 15;
    int hi = w16 >> 3, t = (w16 & 7) >> 1, q = hi * 2 + (w16 & 1);
    return s * 32 + t * 8 + step * 4 + q;
}
// inverse: logical k from slab s, phys pos p (<40); -1 for pad
__device__ __forceinline__ int kfp(int s, int p) {
    if (p >= 32) return -1;
    int t = p >> 3, rem = p & 7, step = rem >> 2, q = rem & 3;
    int w16 = (q < 2) ? (2 * t + q) : (8 + 2 * t + (q - 2));
    return s * 32 + step * 16 + w16;
}
__device__ __forceinline__ void stage_lin(unsigned dst, const __half* src, int nchunks, int tid) {
    for (int i = tid; i < nchunks; i += NTHR)
        cpa16(dst + (unsigned)(i * 16), (const char*)src + (size_t)i * 16);
    asm volatile("cp.async.commit_group;" ::: "memory");
}

// ---------------- prep kernels ----------------
__global__ void prep_w0(const float* __restrict__ W0, const float* __restrict__ Wc,
                        const float* __restrict__ b0, const float* __restrict__ bc) {
    int idx = blockIdx.x * blockDim.x + threadIdx.x;
    if (idx >= NBLK * 2 * 256 * WPAD) return;
    int p = idx % WPAD, n = (idx / WPAD) & 255, s = (idx / 10240) & 1, b = idx / 20480;
    int k = kfp(s, p);
    float v = 0.0f;
    if (k >= 0) {
        if (k < DF)       v = ((n % 44) >= k) ? W0[(b * 256 + n) * DF + k] : 0.0f;
        else if (k == 45) v = Wc[b * 256 + n];
        else if (k == 46) v = b0[b * 256 + n] + bc[b * 256 + n];
    }
    g_W0h[idx] = __float2half(v);
}
__global__ void prep_wh(const float* __restrict__ Wh) {
    int idx = blockIdx.x * blockDim.x + threadIdx.x;
    if (idx >= NBLK * 2 * 8 * 256 * WPAD) return;
    int p = idx % WPAD, n = (idx / WPAD) & 255, s = (idx / 10240) & 7, bl = idx / 81920;
    int k = kfp(s, p);
    float v = (k >= 0 && ((n % 44) >= (k % 44))) ? Wh[((size_t)(bl * 256 + n)) * 256 + k] : 0.0f;
    g_Whh[idx] = __float2half(v);
}
__global__ void prep_wf(const float* __restrict__ Wf) {
    int idx = blockIdx.x * blockDim.x + threadIdx.x;
    if (idx >= NBLK * NCHK * 8 * FN * WPAD) return;
    int p = idx % WPAD, n = (idx / WPAD) % FN, s = (idx / (FN * WPAD)) & 7;
    int ch = (idx / (FN * WPAD * 8)) % NCHK, b = idx / (FN * WPAD * 8 * NCHK);
    int k = kfp(s, p);
    int fl = n / 24, i = n % 24, f = ch * 4 + fl;
    float v = 0.0f;
    if (k >= 0 && i < 23 && f < DF && f > (k % 44))
        v = Wf[((size_t)(b * DM + f * 23 + i)) * 256 + k];
    g_Wfh[idx] = __float2half(v);
}

// ---------------- dense layer: [128 x 256] = A[128 x K] * W[K x 256] ----------------
template<int KSLABS, bool RELU>
__device__ __forceinline__ void dense(const __half* __restrict__ Wg,
                                      const float* __restrict__ bias,
                                      const __half* __restrict__ Asrc, int astr,
                                      __half* __restrict__ dst,
                                      __half* wreg, unsigned wreg_sm, int tid)
{
    const int lane = tid & 31, w = tid >> 5;
    const int wm = w & 3, wn = w >> 2, g = lane >> 2, t = lane & 3;
    const int SLABH = 256 * WPAD;         // halves per slab
    const int SLABC = SLABH * 2 / 16;     // 1280 16B chunks

    float acc[2][8][4];
    #pragma unroll
    for (int mt = 0; mt < 2; mt++)
        #pragma unroll
        for (int nt = 0; nt < 8; nt++)
            acc[mt][nt][0] = acc[mt][nt][1] = acc[mt][nt][2] = acc[mt][nt][3] = 0.0f;

    stage_lin(wreg_sm, Wg, SLABC, tid);
    stage_lin(wreg_sm + SLABH * 2, Wg + SLABH, SLABC, tid);

    for (int s = 0; s < KSLABS; s++) {
        if (s < KSLABS - 1) asm volatile("cp.async.wait_group 1;" ::: "memory");
        else                asm volatile("cp.async.wait_group 0;" ::: "memory");
        __syncthreads();
        const __half* Ws = wreg + (s & 1) * SLABH;
        uint4 Av[4];
        {
            const __half* ap = Asrc + (wm * 32 + g) * astr + s * 32 + t * 8;
            Av[0] = *(const uint4*)ap;
            Av[1] = *(const uint4*)(ap + 8 * astr);
            Av[2] = *(const uint4*)(ap + 16 * astr);
            Av[3] = *(const uint4*)(ap + 24 * astr);
        }
        #pragma unroll
        for (int nt = 0; nt < 8; nt++) {
            const uint4 Bv = *(const uint4*)(Ws + (wn * 64 + nt * 8 + g) * WPAD + t * 8);
            mma16(acc[0][nt], Av[0].x, Av[1].x, Av[0].y, Av[1].y, Bv.x, Bv.y);
            mma16(acc[1][nt], Av[2].x, Av[3].x, Av[2].y, Av[3].y, Bv.x, Bv.y);
            mma16(acc[0][nt], Av[0].z, Av[1].z, Av[0].w, Av[1].w, Bv.z, Bv.w);
            mma16(acc[1][nt], Av[2].z, Av[3].z, Av[2].w, Av[3].w, Bv.z, Bv.w);
        }
        __syncthreads();
        if (s + 2 < KSLABS)
            stage_lin(wreg_sm + (s & 1) * SLABH * 2, Wg + (size_t)(s + 2) * SLABH, SLABC, tid);
    }
    // epilogue: all A reads done at the loop's trailing barrier; in-place write safe
    #pragma unroll
    for (int nt = 0; nt < 8; nt++) {
        int c0 = wn * 64 + nt * 8 + 2 * t;
        int pos = acol(c0);
        float bx = 0.0f, by = 0.0f;
        if (RELU) { float2 bb = *(const float2*)(bias + c0); bx = bb.x; by = bb.y; }
        #pragma unroll
        for (int mt = 0; mt < 2; mt++) {
            int r0 = wm * 32 + mt * 16 + g;
            float v0 = acc[mt][nt][0] + bx, v1 = acc[mt][nt][1] + by;
            float v2 = acc[mt][nt][2] + bx, v3 = acc[mt][nt][3] + by;
            if (RELU) {
                v0 = fmaxf(v0, 0.0f); v1 = fmaxf(v1, 0.0f);
                v2 = fmaxf(v2, 0.0f); v3 = fmaxf(v3, 0.0f);
            }
            *(half2*)(dst + r0 * AS16 + pos)       = __floats2half2_rn(v0, v1);
            *(half2*)(dst + (r0 + 8) * AS16 + pos) = __floats2half2_rn(v2, v3);
        }
    }
    __syncthreads();
}

// ---------------- f-layer chunk: [128 x 96] = act[128 x 256] * Wf[256 x 96] ----------------
__device__ __forceinline__ void f_chunk(const __half* __restrict__ Wg,
                                        const __half* __restrict__ act, float* __restrict__ par,
                                        __half* wreg, unsigned wreg_sm, int tid)
{
    const int lane = tid & 31, w = tid >> 5;
    const int wm = w & 3, wn = w >> 2, g = lane >> 2, t = lane & 3;
    const int SLABH = FN * WPAD;          // 3840 halves
    const int SLABC = SLABH * 2 / 16;     // 480 chunks

    float acc[2][3][4];
    #pragma unroll
    for (int mt = 0; mt < 2; mt++)
        #pragma unroll
        for (int nt = 0; nt < 3; nt++)
            acc[mt][nt][0] = acc[mt][nt][1] = acc[mt][nt][2] = acc[mt][nt][3] = 0.0f;

    stage_lin(wreg_sm, Wg, SLABC, tid);
    stage_lin(wreg_sm + SLABH * 2, Wg + SLABH, SLABC, tid);

    for (int s = 0; s < 8; s++) {
        if (s < 7) asm volatile("cp.async.wait_group 1;" ::: "memory");
        else       asm volatile("cp.async.wait_group 0;" ::: "memory");
        __syncthreads();
        const __half* Ws = wreg + (s & 1) * SLABH;
        uint4 Av[4];
        {
            const __half* ap = act + (wm * 32 + g) * AS16 + s * 32 + t * 8;
            Av[0] = *(const uint4*)ap;
            Av[1] = *(const uint4*)(ap + 8 * AS16);
            Av[2] = *(const uint4*)(ap + 16 * AS16);
            Av[3] = *(const uint4*)(ap + 24 * AS16);
        }
        #pragma unroll
        for (int nt = 0; nt < 3; nt++) {
            const uint4 Bv = *(const uint4*)(Ws + (wn * 24 + nt * 8 + g) * WPAD + t * 8);
            mma16(acc[0][nt], Av[0].x, Av[1].x, Av[0].y, Av[1].y, Bv.x, Bv.y);
            mma16(acc[1][nt], Av[2].x, Av[3].x, Av[2].y, Av[3].y, Bv.x, Bv.y);
            mma16(acc[0][nt], Av[0].z, Av[1].z, Av[0].w, Av[1].w, Bv.z, Bv.w);
            mma16(acc[1][nt], Av[2].z, Av[3].z, Av[2].w, Av[3].w, Bv.z, Bv.w);
        }
        __syncthreads();
        if (s + 2 < 8)
            stage_lin(wreg_sm + (s & 1) * SLABH * 2, Wg + (size_t)(s + 2) * SLABH, SLABC, tid);
    }
    #pragma unroll
    for (int nt = 0; nt < 3; nt++) {
        int c0 = wn * 24 + nt * 8 + 2 * t;
        #pragma unroll
        for (int mt = 0; mt < 2; mt++) {
            int r0 = wm * 32 + mt * 16 + g;
            *(float2*)(par + r0 * PSTR + c0)       = make_float2(acc[mt][nt][0], acc[mt][nt][1]);
            *(float2*)(par + (r0 + 8) * PSTR + c0) = make_float2(acc[mt][nt][2], acc[mt][nt][3]);
        }
    }
    __syncthreads();
}

// ---------------- rational-quadratic spline, K=8 bins ----------------
__device__ __forceinline__ float2 rq_spline(const float* __restrict__ p, float x)
{
    const float TAIL = 13.815510557964274f;
    const float INVS = 0.0625f;
    bool inside = (x >= -TAIL) && (x <= TAIL);
    float xc = fminf(fmaxf(x, -TAIL), TAIL);

    float ew[8], eh[8], mw = -1e30f, mh = -1e30f;
    #pragma unroll
    for (int i = 0; i < 8; i++) {
        float a = p[i] * INVS, bb = p[8 + i] * INVS;
        ew[i] = a; eh[i] = bb;
        mw = fmaxf(mw, a); mh = fmaxf(mh, bb);
    }
    float sw = 0.0f, sh = 0.0f;
    #pragma unroll
    for (int i = 0; i < 8; i++) {
        ew[i] = __expf(ew[i] - mw);  sw += ew[i];
        eh[i] = __expf(eh[i] - mh);  sh += eh[i];
    }
    float iw = 1.0f / sw, ih = 1.0f / sh;

    float d[9]; d[0] = 1.0f; d[8] = 1.0f;
    #pragma unroll
    for (int i = 0; i < 7; i++) {
        float u = p[16 + i];
        d[i + 1] = 1e-3f + fmaxf(u, 0.0f) + log1pf(__expf(-fabsf(u)));
    }

    float cumw = 0.0f, cumh = 0.0f, cwl = -TAIL, chl = -TAIL;
    float bcwl = -TAIL, bw = 1.0f, bchl = -TAIL, bh2 = 1.0f, bd0 = 1.0f, bd1 = 1.0f;
    #pragma unroll
    for (int i = 0; i < 8; i++) {
        cumw += 1e-3f + 0.992f * (ew[i] * iw);
        cumh += 1e-3f + 0.992f * (eh[i] * ih);
        float cwr = (i == 7) ? TAIL : fmaf(2.0f * TAIL, cumw, -TAIL);
        float chr = (i == 7) ? TAIL : fmaf(2.0f * TAIL, cumh, -TAIL);
        if (xc >= cwl) { bcwl = cwl; bw = cwr - cwl; bchl = chl; bh2 = chr - chl; bd0 = d[i]; bd1 = d[i + 1]; }
        cwl = cwr; chl = chr;
    }

    float th  = (xc - bcwl) / bw;
    float th1 = th * (1.0f - th);
    float dl  = bh2 / bw;
    float den = dl + (bd0 + bd1 - 2.0f * dl) * th1;
    float y   = bchl + bh2 * (dl * th * th + bd0 * th1) / den;
    float omt = 1.0f - th;
    float ln  = dl * dl * (bd1 * th * th + 2.0f * dl * th1 + bd0 * omt * omt);
    float lad = __logf(ln) - 2.0f * __logf(den);
    float2 r; r.x = inside ? y : x; r.y = inside ? lad : 0.0f;
    return r;
}

// ---------------- main fused kernel ----------------
__global__ void __launch_bounds__(NTHR, 1)
maf_kernel(const float* __restrict__ x, const float* __restrict__ cond,
           const float* __restrict__ bh, const float* __restrict__ bf,
           float* __restrict__ out)
{
    extern __shared__ char smc[];
    float*  z32  = (float*)(smc + OB_Z32);   // [128][49]
    __half* z16  = (__half*)(smc + OB_Z16);  // [128][72]
    float*  ld_s = (float*)(smc + OB_LD);    // [128]
    __half* act  = (__half*)(smc + OB_ACT);  // [128][264]
    __half* wreg = (__half*)(smc + OB_WRG);
    float*  par  = (float*)(smc + OB_PAR);   // [128][98]
    const unsigned wreg_sm = smem_u32(wreg);

    const int tid  = threadIdx.x;
    const int row0 = blockIdx.x * MROWS;

    for (int i = tid; i < MROWS * DF; i += NTHR) {
        int r = i / DF, f = i - r * DF;
        z32[r * Z32S + f] = x[(row0 + r) * DF + f];
    }
    for (int i = tid; i < MROWS * 64; i += NTHR) {
        int r = i >> 6, f = i & 63;
        float v = (f < DF) ? x[(row0 + r) * DF + f]
                 : (f == 45) ? cond[row0 + r]
                 : (f == 46) ? 1.0f : 0.0f;
        z16[r * Z16S + acol(f)] = __float2half(v);
    }
    if (tid < MROWS) ld_s[tid] = 0.0f;
    __syncthreads();

    for (int b = 0; b < NBLK; b++) {
        dense<2, false>(g_W0h + (size_t)b * 2 * 256 * WPAD, nullptr,
                        z16, Z16S, act, wreg, wreg_sm, tid);
        dense<8, true>(g_Whh + (size_t)(b * 2 + 0) * 8 * 256 * WPAD, bh + (b * 2 + 0) * 256,
                       act, AS16, act, wreg, wreg_sm, tid);
        dense<8, true>(g_Whh + (size_t)(b * 2 + 1) * 8 * 256 * WPAD, bh + (b * 2 + 1) * 256,
                       act, AS16, act, wreg, wreg_sm, tid);

        for (int ch = 0; ch < NCHK; ch++) {
            f_chunk(g_Wfh + (size_t)(b * NCHK + ch) * 8 * FN * WPAD, act, par, wreg, wreg_sm, tid);
            {
                int r = tid & 127, fl = tid >> 7, f = ch * 4 + fl;
                if (f < DF) {
                    float p[23];
                    const float* bfp = bf + b * DM + f * 23;
                    const float* pp  = par + r * PSTR + fl * 24;
                    #pragma unroll
                    for (int i = 0; i < 23; i++) p[i] = pp[i] + bfp[i];
                    float xv = z32[r * Z32S + f];
                    float2 yr = rq_spline(p, xv);
                    z32[r * Z32S + f] = yr.x;
                    z16[r * Z16S + acol(f)] = __float2half(yr.x);
                    atomicAdd(&ld_s[r], yr.y);
                }
            }
            __syncthreads();
        }
    }

    if (tid < MROWS) {
        float s = 0.0f;
        #pragma unroll
        for (int f = 0; f < DF; f++) { float v = z32[tid * Z32S + f]; s = fmaf(v, v, s); }
        out[row0 + tid] = -0.5f * s - 41.35223399420827f + ld_s[tid];
    }
}

// ---------------- launch ----------------
extern "C" void kernel_launch(void* const* d_in, const int* in_sizes, int n_in,
                              void* d_out, int out_size) {
    const float* x    = (const float*)d_in[0];
    const float* cond = (const float*)d_in[1];
    const float* W0   = (const float*)d_in[2];
    const float* b0   = (const float*)d_in[3];
    const float* Wc   = (const float*)d_in[4];
    const float* bc   = (const float*)d_in[5];
    const float* Wh   = (const float*)d_in[6];
    const float* bh   = (const float*)d_in[7];
    const float* Wf   = (const float*)d_in[8];
    const float* bf   = (const float*)d_in[9];
    float* out = (float*)d_out;
    const int B = in_sizes[0] / DF;

    prep_w0<<<(NBLK * 2 * 256 * WPAD + 255) / 256, 256>>>(W0, Wc, b0, bc);
    prep_wh<<<(NBLK * 2 * 8 * 256 * WPAD + 255) / 256, 256>>>(Wh);
    prep_wf<<<(NBLK * NCHK * 8 * FN * WPAD + 255) / 256, 256>>>(Wf);

    cudaFuncSetAttribute(maf_kernel, cudaFuncAttributeMaxDynamicSharedMemorySize, SMEM_BYTES);
    maf_kernel<<<B / MROWS, NTHR, SMEM_BYTES>>>(x, cond, bh, bf, out);
}

// round 9
// speedup vs baseline: 7.7229x; 1.2088x over previous
#include <cuda_runtime.h>
#include <cuda_fp16.h>

// ---------------- problem constants ----------------
#define NBLK 6
#define DF   45
#define DM   1035
#define MROWS 128
#define NTHR 512

#define Z32S 49            // fp32 z row stride
#define Z16S 72            // fp16 z row stride (halves), 64 cols (2 k-slabs)
#define AS16 264           // fp16 act row stride (halves), 256 cols (8 k-slabs)
#define WPAD 40            // halves per k-slab row (32 data + 8 pad)
#define FN   192           // f-chunk cols (8 features x 24)
#define NCHK 6             // f chunks
#define PSTR 202           // fp16 params row stride (halves), odd-word for bank spread

// smem byte offsets
#define OB_Z32 0
#define OB_Z16 25088                   // 128*49*4
#define OB_LD  (OB_Z16 + 18432)        // 128*72*2
#define OB_ACT (OB_LD + 512)
#define OB_WRG (OB_ACT + 67584)        // 128*264*2
#define OB_PAR (OB_WRG + 61440)        // 3 x 20480 hidden slabs (f uses 3 x 15360 inside)
#define SMEM_BYTES (OB_PAR + 51712)    // 128*202*2 -> 224768 total

// ---------------- device weight images (masked, slab-blocked, interleaved, fp16) ----------------
__device__ __half g_W0h[NBLK * 2 * 256 * WPAD];
__device__ __half g_Whh[NBLK * 2 * 8 * 256 * WPAD];
__device__ __half g_Wfh[NBLK * NCHK * 8 * FN * WPAD];

// ---------------- helpers ----------------
__device__ __forceinline__ unsigned smem_u32(const void* p) {
    unsigned a; asm("{ .reg .u64 t; cvta.to.shared.u64 t, %1; cvt.u32.u64 %0, t; }" : "=r"(a) : "l"(p));
    return a;
}
__device__ __forceinline__ void cpa16(unsigned d, const void* s) {
    asm volatile("cp.async.ca.shared.global [%0], [%1], 16;" :: "r"(d), "l"(s));
}
__device__ __forceinline__ void mma16(float* d, unsigned a0, unsigned a1, unsigned a2, unsigned a3,
                                      unsigned b0, unsigned b1) {
    asm volatile("mma.sync.aligned.m16n8k16.row.col.f32.f16.f16.f32 "
        "{%0,%1,%2,%3},{%4,%5,%6,%7},{%8,%9},{%0,%1,%2,%3};"
        : "+f"(d[0]), "+f"(d[1]), "+f"(d[2]), "+f"(d[3])
        : "r"(a0), "r"(a1), "r"(a2), "r"(a3), "r"(b0), "r"(b1));
}
// phys column of logical k within interleaved 32-k slabs
__device__ __forceinline__ int acol(int c) {
    int s = c >> 5, k32 = c & 31, step = k32 >> 4, w16 = k32 & 15;
    int hi = w16 >> 3, t = (w16 & 7) >> 1, q = hi * 2 + (w16 & 1);
    return s * 32 + t * 8 + step * 4 + q;
}
// inverse: logical k from slab s, phys pos p (<40); -1 for pad
__device__ __forceinline__ int kfp(int s, int p) {
    if (p >= 32) return -1;
    int t = p >> 3, rem = p & 7, step = rem >> 2, q = rem & 3;
    int w16 = (q < 2) ? (2 * t + q) : (8 + 2 * t + (q - 2));
    return s * 32 + step * 16 + w16;
}
__device__ __forceinline__ void stage_lin(unsigned dst, const __half* src, int nchunks, int tid) {
    for (int i = tid; i < nchunks; i += NTHR)
        cpa16(dst + (unsigned)(i * 16), (const char*)src + (size_t)i * 16);
    asm volatile("cp.async.commit_group;" ::: "memory");
}

// ---------------- prep kernels ----------------
__global__ void prep_w0(const float* __restrict__ W0, const float* __restrict__ Wc,
                        const float* __restrict__ b0, const float* __restrict__ bc) {
    int idx = blockIdx.x * blockDim.x + threadIdx.x;
    if (idx >= NBLK * 2 * 256 * WPAD) return;
    int p = idx % WPAD, n = (idx / WPAD) & 255, s = (idx / 10240) & 1, b = idx / 20480;
    int k = kfp(s, p);
    float v = 0.0f;
    if (k >= 0) {
        if (k < DF)       v = ((n % 44) >= k) ? W0[(b * 256 + n) * DF + k] : 0.0f;
        else if (k == 45) v = Wc[b * 256 + n];
        else if (k == 46) v = b0[b * 256 + n] + bc[b * 256 + n];
    }
    g_W0h[idx] = __float2half(v);
}
__global__ void prep_wh(const float* __restrict__ Wh) {
    int idx = blockIdx.x * blockDim.x + threadIdx.x;
    if (idx >= NBLK * 2 * 8 * 256 * WPAD) return;
    int p = idx % WPAD, n = (idx / WPAD) & 255, s = (idx / 10240) & 7, bl = idx / 81920;
    int k = kfp(s, p);
    float v = (k >= 0 && ((n % 44) >= (k % 44))) ? Wh[((size_t)(bl * 256 + n)) * 256 + k] : 0.0f;
    g_Whh[idx] = __float2half(v);
}
__global__ void prep_wf(const float* __restrict__ Wf) {
    int idx = blockIdx.x * blockDim.x + threadIdx.x;
    if (idx >= NBLK * NCHK * 8 * FN * WPAD) return;
    int p = idx % WPAD, n = (idx / WPAD) % FN, s = (idx / (FN * WPAD)) & 7;
    int ch = (idx / (FN * WPAD * 8)) % NCHK, b = idx / (FN * WPAD * 8 * NCHK);
    int k = kfp(s, p);
    int fl = n / 24, i = n % 24, f = ch * 8 + fl;
    float v = 0.0f;
    if (k >= 0 && i < 23 && f < DF && f > (k % 44))
        v = Wf[((size_t)(b * DM + f * 23 + i)) * 256 + k];
    g_Wfh[idx] = __float2half(v);
}

// ---------------- dense layer: [128 x 256] = A[128 x K] * W[K x 256] ----------------
// triple-buffered weight slabs, ONE barrier per slab
template<int KSLABS, bool RELU>
__device__ __forceinline__ void dense(const __half* __restrict__ Wg,
                                      const float* __restrict__ bias,
                                      const __half* __restrict__ Asrc, int astr,
                                      __half* __restrict__ dst,
                                      __half* wreg, unsigned wreg_sm, int tid)
{
    const int lane = tid & 31, w = tid >> 5;
    const int wm = w & 3, wn = w >> 2, g = lane >> 2, t = lane & 3;
    const int SLABH = 256 * WPAD;          // halves per slab (10240)
    const int SLABB = SLABH * 2;           // bytes (20480)
    const int SLABC = SLABB / 16;          // 16B chunks (1280)

    float acc[2][8][4];
    #pragma unroll
    for (int mt = 0; mt < 2; mt++)
        #pragma unroll
        for (int nt = 0; nt < 8; nt++)
            acc[mt][nt][0] = acc[mt][nt][1] = acc[mt][nt][2] = acc[mt][nt][3] = 0.0f;

    stage_lin(wreg_sm, Wg, SLABC, tid);
    stage_lin(wreg_sm + SLABB, Wg + SLABH, SLABC, tid);

    #pragma unroll
    for (int s = 0; s < KSLABS; s++) {
        if (s < KSLABS - 1) asm volatile("cp.async.wait_group 1;" ::: "memory");
        else                asm volatile("cp.async.wait_group 0;" ::: "memory");
        __syncthreads();   // slab s visible everywhere; everyone done with slab s-1
        if (s + 2 < KSLABS)
            stage_lin(wreg_sm + ((s + 2) % 3) * SLABB, Wg + (size_t)(s + 2) * SLABH, SLABC, tid);
        const __half* Ws = wreg + (s % 3) * SLABH;
        uint4 Av[4];
        {
            const __half* ap = Asrc + (wm * 32 + g) * astr + s * 32 + t * 8;
            Av[0] = *(const uint4*)ap;
            Av[1] = *(const uint4*)(ap + 8 * astr);
            Av[2] = *(const uint4*)(ap + 16 * astr);
            Av[3] = *(const uint4*)(ap + 24 * astr);
        }
        #pragma unroll
        for (int nt = 0; nt < 8; nt++) {
            const uint4 Bv = *(const uint4*)(Ws + (wn * 64 + nt * 8 + g) * WPAD + t * 8);
            mma16(acc[0][nt], Av[0].x, Av[1].x, Av[0].y, Av[1].y, Bv.x, Bv.y);
            mma16(acc[1][nt], Av[2].x, Av[3].x, Av[2].y, Av[3].y, Bv.x, Bv.y);
            mma16(acc[0][nt], Av[0].z, Av[1].z, Av[0].w, Av[1].w, Bv.z, Bv.w);
            mma16(acc[1][nt], Av[2].z, Av[3].z, Av[2].w, Av[3].w, Bv.z, Bv.w);
        }
    }
    __syncthreads();   // all A reads complete -> in-place write of act is safe
    #pragma unroll
    for (int nt = 0; nt < 8; nt++) {
        int c0 = wn * 64 + nt * 8 + 2 * t;
        int pos = acol(c0);
        float bx = 0.0f, by = 0.0f;
        if (RELU) { float2 bb = *(const float2*)(bias + c0); bx = bb.x; by = bb.y; }
        #pragma unroll
        for (int mt = 0; mt < 2; mt++) {
            int r0 = wm * 32 + mt * 16 + g;
            float v0 = acc[mt][nt][0] + bx, v1 = acc[mt][nt][1] + by;
            float v2 = acc[mt][nt][2] + bx, v3 = acc[mt][nt][3] + by;
            if (RELU) {
                v0 = fmaxf(v0, 0.0f); v1 = fmaxf(v1, 0.0f);
                v2 = fmaxf(v2, 0.0f); v3 = fmaxf(v3, 0.0f);
            }
            *(half2*)(dst + r0 * AS16 + pos)       = __floats2half2_rn(v0, v1);
            *(half2*)(dst + (r0 + 8) * AS16 + pos) = __floats2half2_rn(v2, v3);
        }
    }
    // no trailing barrier: the next layer's first in-loop barrier orders act writes vs reads
}

// ---------------- f-layer chunk: [128 x 192] = act[128 x 256] * Wf[256 x 192] ----------------
__device__ __forceinline__ void f_chunk(const __half* __restrict__ Wg,
                                        const __half* __restrict__ act, __half* __restrict__ par,
                                        __half* wreg, unsigned wreg_sm, int tid)
{
    const int lane = tid & 31, w = tid >> 5;
    const int wm = w & 3, wn = w >> 2, g = lane >> 2, t = lane & 3;
    const int SLABH = FN * WPAD;           // 7680 halves
    const int SLABB = SLABH * 2;           // 15360 bytes
    const int SLABC = SLABB / 16;          // 960 chunks

    float acc[2][6][4];
    #pragma unroll
    for (int mt = 0; mt < 2; mt++)
        #pragma unroll
        for (int nt = 0; nt < 6; nt++)
            acc[mt][nt][0] = acc[mt][nt][1] = acc[mt][nt][2] = acc[mt][nt][3] = 0.0f;

    stage_lin(wreg_sm, Wg, SLABC, tid);
    stage_lin(wreg_sm + SLABB, Wg + SLABH, SLABC, tid);

    #pragma unroll
    for (int s = 0; s < 8; s++) {
        if (s < 7) asm volatile("cp.async.wait_group 1;" ::: "memory");
        else       asm volatile("cp.async.wait_group 0;" ::: "memory");
        __syncthreads();
        if (s + 2 < 8)
            stage_lin(wreg_sm + ((s + 2) % 3) * SLABB, Wg + (size_t)(s + 2) * SLABH, SLABC, tid);
        const __half* Ws = wreg + (s % 3) * SLABH;
        uint4 Av[4];
        {
            const __half* ap = act + (wm * 32 + g) * AS16 + s * 32 + t * 8;
            Av[0] = *(const uint4*)ap;
            Av[1] = *(const uint4*)(ap + 8 * AS16);
            Av[2] = *(const uint4*)(ap + 16 * AS16);
            Av[3] = *(const uint4*)(ap + 24 * AS16);
        }
        #pragma unroll
        for (int nt = 0; nt < 6; nt++) {
            const uint4 Bv = *(const uint4*)(Ws + (wn * 48 + nt * 8 + g) * WPAD + t * 8);
            mma16(acc[0][nt], Av[0].x, Av[1].x, Av[0].y, Av[1].y, Bv.x, Bv.y);
            mma16(acc[1][nt], Av[2].x, Av[3].x, Av[2].y, Av[3].y, Bv.x, Bv.y);
            mma16(acc[0][nt], Av[0].z, Av[1].z, Av[0].w, Av[1].w, Bv.z, Bv.w);
            mma16(acc[1][nt], Av[2].z, Av[3].z, Av[2].w, Av[3].w, Bv.z, Bv.w);
        }
    }
    // epilogue writes par (not read by anyone until the caller's barrier)
    #pragma unroll
    for (int nt = 0; nt < 6; nt++) {
        int c0 = wn * 48 + nt * 8 + 2 * t;
        #pragma unroll
        for (int mt = 0; mt < 2; mt++) {
            int r0 = wm * 32 + mt * 16 + g;
            *(half2*)(par + r0 * PSTR + c0)       = __floats2half2_rn(acc[mt][nt][0], acc[mt][nt][1]);
            *(half2*)(par + (r0 + 8) * PSTR + c0) = __floats2half2_rn(acc[mt][nt][2], acc[mt][nt][3]);
        }
    }
}

// ---------------- rational-quadratic spline, K=8 bins ----------------
__device__ __forceinline__ float2 rq_spline(const float* __restrict__ p, float x)
{
    const float TAIL = 13.815510557964274f;
    const float INVS = 0.0625f;
    bool inside = (x >= -TAIL) && (x <= TAIL);
    float xc = fminf(fmaxf(x, -TAIL), TAIL);

    float ew[8], eh[8], mw = -1e30f, mh = -1e30f;
    #pragma unroll
    for (int i = 0; i < 8; i++) {
        float a = p[i] * INVS, bb = p[8 + i] * INVS;
        ew[i] = a; eh[i] = bb;
        mw = fmaxf(mw, a); mh = fmaxf(mh, bb);
    }
    float sw = 0.0f, sh = 0.0f;
    #pragma unroll
    for (int i = 0; i < 8; i++) {
        ew[i] = __expf(ew[i] - mw);  sw += ew[i];
        eh[i] = __expf(eh[i] - mh);  sh += eh[i];
    }
    float iw = 1.0f / sw, ih = 1.0f / sh;

    float d[9]; d[0] = 1.0f; d[8] = 1.0f;
    #pragma unroll
    for (int i = 0; i < 7; i++) {
        float u = p[16 + i];
        d[i + 1] = 1e-3f + fmaxf(u, 0.0f) + log1pf(__expf(-fabsf(u)));
    }

    float cumw = 0.0f, cumh = 0.0f, cwl = -TAIL, chl = -TAIL;
    float bcwl = -TAIL, bw = 1.0f, bchl = -TAIL, bh2 = 1.0f, bd0 = 1.0f, bd1 = 1.0f;
    #pragma unroll
    for (int i = 0; i < 8; i++) {
        cumw += 1e-3f + 0.992f * (ew[i] * iw);
        cumh += 1e-3f + 0.992f * (eh[i] * ih);
        float cwr = (i == 7) ? TAIL : fmaf(2.0f * TAIL, cumw, -TAIL);
        float chr = (i == 7) ? TAIL : fmaf(2.0f * TAIL, cumh, -TAIL);
        if (xc >= cwl) { bcwl = cwl; bw = cwr - cwl; bchl = chl; bh2 = chr - chl; bd0 = d[i]; bd1 = d[i + 1]; }
        cwl = cwr; chl = chr;
    }

    float th  = (xc - bcwl) / bw;
    float th1 = th * (1.0f - th);
    float dl  = bh2 / bw;
    float den = dl + (bd0 + bd1 - 2.0f * dl) * th1;
    float y   = bchl + bh2 * (dl * th * th + bd0 * th1) / den;
    float omt = 1.0f - th;
    float ln  = dl * dl * (bd1 * th * th + 2.0f * dl * th1 + bd0 * omt * omt);
    float lad = __logf(ln) - 2.0f * __logf(den);
    float2 r; r.x = inside ? y : x; r.y = inside ? lad : 0.0f;
    return r;
}

// ---------------- main fused kernel ----------------
__global__ void __launch_bounds__(NTHR, 1)
maf_kernel(const float* __restrict__ x, const float* __restrict__ cond,
           const float* __restrict__ bh, const float* __restrict__ bf,
           float* __restrict__ out)
{
    extern __shared__ char smc[];
    float*  z32  = (float*)(smc + OB_Z32);   // [128][49]
    __half* z16  = (__half*)(smc + OB_Z16);  // [128][72]
    float*  ld_s = (float*)(smc + OB_LD);    // [128]
    __half* act  = (__half*)(smc + OB_ACT);  // [128][264]
    __half* wreg = (__half*)(smc + OB_WRG);  // 3 slabs
    __half* par  = (__half*)(smc + OB_PAR);  // [128][202]
    const unsigned wreg_sm = smem_u32(wreg);

    const int tid  = threadIdx.x;
    const int row0 = blockIdx.x * MROWS;

    for (int i = tid; i < MROWS * DF; i += NTHR) {
        int r = i / DF, f = i - r * DF;
        z32[r * Z32S + f] = x[(row0 + r) * DF + f];
    }
    for (int i = tid; i < MROWS * 64; i += NTHR) {
        int r = i >> 6, f = i & 63;
        float v = (f < DF) ? x[(row0 + r) * DF + f]
                 : (f == 45) ? cond[row0 + r]
                 : (f == 46) ? 1.0f : 0.0f;
        z16[r * Z16S + acol(f)] = __float2half(v);
    }
    if (tid < MROWS) ld_s[tid] = 0.0f;
    // ordering provided by first dense's in-loop barrier

    for (int b = 0; b < NBLK; b++) {
        dense<2, false>(g_W0h + (size_t)b * 2 * 256 * WPAD, nullptr,
                        z16, Z16S, act, wreg, wreg_sm, tid);
        dense<8, true>(g_Whh + (size_t)(b * 2 + 0) * 8 * 256 * WPAD, bh + (b * 2 + 0) * 256,
                       act, AS16, act, wreg, wreg_sm, tid);
        dense<8, true>(g_Whh + (size_t)(b * 2 + 1) * 8 * 256 * WPAD, bh + (b * 2 + 1) * 256,
                       act, AS16, act, wreg, wreg_sm, tid);

        for (int ch = 0; ch < NCHK; ch++) {
            f_chunk(g_Wfh + (size_t)(b * NCHK + ch) * 8 * FN * WPAD, act, par, wreg, wreg_sm, tid);
            __syncthreads();   // par epilogue visible before spline reads
            {
                int r = tid & 127, flb = tid >> 7;   // flb in 0..3; handle flb and flb+4
                float lsum = 0.0f;
                #pragma unroll
                for (int q = 0; q < 2; q++) {
                    int fl = flb + q * 4;
                    int f = ch * 8 + fl;
                    if (f < DF) {
                        float p[23];
                        const float* bfp = bf + b * DM + f * 23;
                        const __half* pp = par + r * PSTR + fl * 24;
                        #pragma unroll
                        for (int i = 0; i < 23; i++)
                            p[i] = __half2float(pp[i]) + bfp[i];
                        float xv = z32[r * Z32S + f];
                        float2 yr = rq_spline(p, xv);
                        z32[r * Z32S + f] = yr.x;
                        z16[r * Z16S + acol(f)] = __float2half(yr.x);
                        lsum += yr.y;
                    }
                }
                if (lsum != 0.0f) atomicAdd(&ld_s[r], lsum);
            }
            // no trailing barrier: next f_chunk/dense in-loop barriers order everything
        }
    }

    __syncthreads();
    if (tid < MROWS) {
        float s = 0.0f;
        #pragma unroll
        for (int f = 0; f < DF; f++) { float v = z32[tid * Z32S + f]; s = fmaf(v, v, s); }
        out[row0 + tid] = -0.5f * s - 41.35223399420827f + ld_s[tid];
    }
}

// ---------------- launch ----------------
extern "C" void kernel_launch(void* const* d_in, const int* in_sizes, int n_in,
                              void* d_out, int out_size) {
    const float* x    = (const float*)d_in[0];
    const float* cond = (const float*)d_in[1];
    const float* W0   = (const float*)d_in[2];
    const float* b0   = (const float*)d_in[3];
    const float* Wc   = (const float*)d_in[4];
    const float* bc   = (const float*)d_in[5];
    const float* Wh   = (const float*)d_in[6];
    const float* bh   = (const float*)d_in[7];
    const float* Wf   = (const float*)d_in[8];
    const float* bf   = (const float*)d_in[9];
    float* out = (float*)d_out;
    const int B = in_sizes[0] / DF;

    prep_w0<<<(NBLK * 2 * 256 * WPAD + 255) / 256, 256>>>(W0, Wc, b0, bc);
    prep_wh<<<(NBLK * 2 * 8 * 256 * WPAD + 255) / 256, 256>>>(Wh);
    prep_wf<<<(NBLK * NCHK * 8 * FN * WPAD + 255) / 256, 256>>>(Wf);

    cudaFuncSetAttribute(maf_kernel, cudaFuncAttributeMaxDynamicSharedMemorySize, SMEM_BYTES);
    maf_kernel<<<B / MROWS, NTHR, SMEM_BYTES>>>(x, cond, bh, bf, out);
}

// round 10
// speedup vs baseline: 11.3141x; 1.4650x over previous
#include <cuda_runtime.h>
#include <cuda_fp16.h>

// ---------------- problem constants ----------------
#define NBLK 6
#define DF   45
#define DM   1035
#define MROWS 64           // rows per CTA
#define NTHR 256

#define Z32S 49            // fp32 z row stride
#define Z16S 72            // fp16 z row stride (halves), 64 cols (2 k-slabs)
#define AS16 264           // fp16 act row stride (halves), 256 cols (8 k-slabs)
#define FN   192           // f-chunk cols (8 features x 24)
#define NCHK 6             // f chunks
#define PSTR 202           // fp16 params row stride (halves)

// smem byte offsets (total 81664 -> 2 CTAs/SM)
#define OB_Z32 0
#define OB_Z16 12544                  // 64*49*4
#define OB_LD  (OB_Z16 + 9216)        // 64*72*2
#define OB_ACT (OB_LD + 256)
#define OB_PAR (OB_ACT + 33792)       // 64*264*2
#define SMEM_BYTES (OB_PAR + 25856)   // 64*202*2 -> 81664

// ---------------- device weight images (masked, k-interleaved, LDG-fragment layout) ----------------
// dense slab: [slab][col 256][32 k-halves]; f slab: [slab][col 192][32]
__device__ __half g_W0p[NBLK * 2 * 256 * 32];
__device__ __half g_Whp[NBLK * 2 * 8 * 256 * 32];
__device__ __half g_Wfp[NBLK * NCHK * 8 * FN * 32];

// ---------------- helpers ----------------
__device__ __forceinline__ void mma16(float* d, unsigned a0, unsigned a1, unsigned a2, unsigned a3,
                                      unsigned b0, unsigned b1) {
    asm volatile("mma.sync.aligned.m16n8k16.row.col.f32.f16.f16.f32 "
        "{%0,%1,%2,%3},{%4,%5,%6,%7},{%8,%9},{%0,%1,%2,%3};"
        : "+f"(d[0]), "+f"(d[1]), "+f"(d[2]), "+f"(d[3])
        : "r"(a0), "r"(a1), "r"(a2), "r"(a3), "r"(b0), "r"(b1));
}
// phys column of logical k within interleaved 32-k slabs (A-side layout)
__device__ __forceinline__ int acol(int c) {
    int s = c >> 5, k32 = c & 31, step = k32 >> 4, w16 = k32 & 15;
    int hi = w16 >> 3, t = (w16 & 7) >> 1, q = hi * 2 + (w16 & 1);
    return s * 32 + t * 8 + step * 4 + q;
}
// logical k from slab s, phys pos p (<32)
__device__ __forceinline__ int kfp2(int s, int p) {
    int t = p >> 3, rem = p & 7, step = rem >> 2, q = rem & 3;
    int w16 = (q < 2) ? (2 * t + q) : (8 + 2 * t + (q - 2));
    return s * 32 + step * 16 + w16;
}

// ---------------- prep kernels ----------------
__global__ void prep_w0(const float* __restrict__ W0, const float* __restrict__ Wc,
                        const float* __restrict__ b0, const float* __restrict__ bc) {
    int idx = blockIdx.x * blockDim.x + threadIdx.x;
    if (idx >= NBLK * 2 * 256 * 32) return;
    int p = idx & 31, n = (idx >> 5) & 255, s = (idx >> 13) & 1, b = idx >> 14;
    int k = kfp2(s, p);
    float v = 0.0f;
    if (k < DF)       v = ((n % 44) >= k) ? W0[(b * 256 + n) * DF + k] : 0.0f;
    else if (k == 45) v = Wc[b * 256 + n];
    else if (k == 46) v = b0[b * 256 + n] + bc[b * 256 + n];
    g_W0p[idx] = __float2half(v);
}
__global__ void prep_wh(const float* __restrict__ Wh) {
    int idx = blockIdx.x * blockDim.x + threadIdx.x;
    if (idx >= NBLK * 2 * 8 * 256 * 32) return;
    int p = idx & 31, n = (idx >> 5) & 255, s = (idx >> 13) & 7, bl = idx >> 16;
    int k = kfp2(s, p);
    float v = ((n % 44) >= (k % 44)) ? Wh[((size_t)(bl * 256 + n)) * 256 + k] : 0.0f;
    g_Whp[idx] = __float2half(v);
}
__global__ void prep_wf(const float* __restrict__ Wf) {
    int idx = blockIdx.x * blockDim.x + threadIdx.x;
    if (idx >= NBLK * NCHK * 8 * FN * 32) return;
    int p = idx & 31, n = (idx >> 5) % FN, s = (idx / (FN * 32)) & 7;
    int ch = (idx / (FN * 32 * 8)) % NCHK, b = idx / (FN * 32 * 8 * NCHK);
    int k = kfp2(s, p);
    int fl = n / 24, i = n % 24, f = ch * 8 + fl;
    float v = 0.0f;
    if (i < 23 && f < DF && f > (k % 44))
        v = Wf[((size_t)(b * DM + f * 23 + i)) * 256 + k];
    g_Wfp[idx] = __float2half(v);
}

// ---------------- dense layer: [64 x 256] = A[64 x K] * W[K x 256], B direct from L2 ----------------
// 8 warps: wm = w&1 (2 x 32 rows), wn = w>>1 (4 x 64 cols); warp tile 32x64
template<int KSLABS, bool RELU, bool INPLACE>
__device__ __forceinline__ void dense(const __half* __restrict__ Wg,
                                      const float* __restrict__ bias,
                                      const __half* __restrict__ Asrc, int astr,
                                      __half* __restrict__ dst, int tid)
{
    const int lane = tid & 31, w = tid >> 5;
    const int wm = w & 1, wn = w >> 1, g = lane >> 2, t = lane & 3;

    float acc[2][8][4];
    #pragma unroll
    for (int mt = 0; mt < 2; mt++)
        #pragma unroll
        for (int nt = 0; nt < 8; nt++)
            acc[mt][nt][0] = acc[mt][nt][1] = acc[mt][nt][2] = acc[mt][nt][3] = 0.0f;

    __syncthreads();   // entry: prior writers of Asrc / prior readers of dst have arrived

    const __half* aprow = Asrc + (wm * 32 + g) * astr + t * 8;
    const __half* bbase = Wg + ((size_t)(wn * 64 + g)) * 32 + t * 8;

    #pragma unroll
    for (int s = 0; s < KSLABS; s++) {
        uint4 Av[4];
        {
            const __half* ap = aprow + s * 32;
            Av[0] = *(const uint4*)ap;
            Av[1] = *(const uint4*)(ap + 8 * astr);
            Av[2] = *(const uint4*)(ap + 16 * astr);
            Av[3] = *(const uint4*)(ap + 24 * astr);
        }
        const __half* bp = bbase + (size_t)s * (256 * 32);
        #pragma unroll
        for (int h = 0; h < 2; h++) {
            uint4 Bv[4];
            #pragma unroll
            for (int j = 0; j < 4; j++)
                Bv[j] = *(const uint4*)(bp + (h * 4 + j) * (8 * 32));
            #pragma unroll
            for (int j = 0; j < 4; j++) {
                int nt = h * 4 + j;
                mma16(acc[0][nt], Av[0].x, Av[1].x, Av[0].y, Av[1].y, Bv[j].x, Bv[j].y);
                mma16(acc[1][nt], Av[2].x, Av[3].x, Av[2].y, Av[3].y, Bv[j].x, Bv[j].y);
                mma16(acc[0][nt], Av[0].z, Av[1].z, Av[0].w, Av[1].w, Bv[j].z, Bv[j].w);
                mma16(acc[1][nt], Av[2].z, Av[3].z, Av[2].w, Av[3].w, Bv[j].z, Bv[j].w);
            }
        }
    }
    if (INPLACE) __syncthreads();   // all A reads done before overwriting act
    #pragma unroll
    for (int nt = 0; nt < 8; nt++) {
        int c0 = wn * 64 + nt * 8 + 2 * t;
        int pos = acol(c0);
        float bx = 0.0f, by = 0.0f;
        if (RELU) { float2 bb = *(const float2*)(bias + c0); bx = bb.x; by = bb.y; }
        #pragma unroll
        for (int mt = 0; mt < 2; mt++) {
            int r0 = wm * 32 + mt * 16 + g;
            float v0 = acc[mt][nt][0] + bx, v1 = acc[mt][nt][1] + by;
            float v2 = acc[mt][nt][2] + bx, v3 = acc[mt][nt][3] + by;
            if (RELU) {
                v0 = fmaxf(v0, 0.0f); v1 = fmaxf(v1, 0.0f);
                v2 = fmaxf(v2, 0.0f); v3 = fmaxf(v3, 0.0f);
            }
            *(half2*)(dst + r0 * AS16 + pos)       = __floats2half2_rn(v0, v1);
            *(half2*)(dst + (r0 + 8) * AS16 + pos) = __floats2half2_rn(v2, v3);
        }
    }
}

// ---------------- f-layer chunk: [64 x 192] = act[64 x 256] * Wf[256 x 192] ----------------
// 8 warps: wm = w&1, wn = w>>1 (4 x 48 cols); warp tile 32x48
__device__ __forceinline__ void f_chunk(const __half* __restrict__ Wg,
                                        const __half* __restrict__ act,
                                        __half* __restrict__ par, int tid)
{
    const int lane = tid & 31, w = tid >> 5;
    const int wm = w & 1, wn = w >> 1, g = lane >> 2, t = lane & 3;

    float acc[2][6][4];
    #pragma unroll
    for (int mt = 0; mt < 2; mt++)
        #pragma unroll
        for (int nt = 0; nt < 6; nt++)
            acc[mt][nt][0] = acc[mt][nt][1] = acc[mt][nt][2] = acc[mt][nt][3] = 0.0f;

    __syncthreads();   // entry: previous spline readers of par have arrived

    const __half* aprow = act + (wm * 32 + g) * AS16 + t * 8;
    const __half* bbase = Wg + ((size_t)(wn * 48 + g)) * 32 + t * 8;

    #pragma unroll
    for (int s = 0; s < 8; s++) {
        uint4 Av[4];
        {
            const __half* ap = aprow + s * 32;
            Av[0] = *(const uint4*)ap;
            Av[1] = *(const uint4*)(ap + 8 * AS16);
            Av[2] = *(const uint4*)(ap + 16 * AS16);
            Av[3] = *(const uint4*)(ap + 24 * AS16);
        }
        const __half* bp = bbase + (size_t)s * (FN * 32);
        #pragma unroll
        for (int h = 0; h < 2; h++) {
            uint4 Bv[3];
            #pragma unroll
            for (int j = 0; j < 3; j++)
                Bv[j] = *(const uint4*)(bp + (h * 3 + j) * (8 * 32));
            #pragma unroll
            for (int j = 0; j < 3; j++) {
                int nt = h * 3 + j;
                mma16(acc[0][nt], Av[0].x, Av[1].x, Av[0].y, Av[1].y, Bv[j].x, Bv[j].y);
                mma16(acc[1][nt], Av[2].x, Av[3].x, Av[2].y, Av[3].y, Bv[j].x, Bv[j].y);
                mma16(acc[0][nt], Av[0].z, Av[1].z, Av[0].w, Av[1].w, Bv[j].z, Bv[j].w);
                mma16(acc[1][nt], Av[2].z, Av[3].z, Av[2].w, Av[3].w, Bv[j].z, Bv[j].w);
            }
        }
    }
    #pragma unroll
    for (int nt = 0; nt < 6; nt++) {
        int c0 = wn * 48 + nt * 8 + 2 * t;
        #pragma unroll
        for (int mt = 0; mt < 2; mt++) {
            int r0 = wm * 32 + mt * 16 + g;
            *(half2*)(par + r0 * PSTR + c0)       = __floats2half2_rn(acc[mt][nt][0], acc[mt][nt][1]);
            *(half2*)(par + (r0 + 8) * PSTR + c0) = __floats2half2_rn(acc[mt][nt][2], acc[mt][nt][3]);
        }
    }
}

// ---------------- rational-quadratic spline, K=8 bins ----------------
__device__ __forceinline__ float2 rq_spline(const float* __restrict__ p, float x)
{
    const float TAIL = 13.815510557964274f;
    const float INVS = 0.0625f;
    bool inside = (x >= -TAIL) && (x <= TAIL);
    float xc = fminf(fmaxf(x, -TAIL), TAIL);

    float ew[8], eh[8], mw = -1e30f, mh = -1e30f;
    #pragma unroll
    for (int i = 0; i < 8; i++) {
        float a = p[i] * INVS, bb = p[8 + i] * INVS;
        ew[i] = a; eh[i] = bb;
        mw = fmaxf(mw, a); mh = fmaxf(mh, bb);
    }
    float sw = 0.0f, sh = 0.0f;
    #pragma unroll
    for (int i = 0; i < 8; i++) {
        ew[i] = __expf(ew[i] - mw);  sw += ew[i];
        eh[i] = __expf(eh[i] - mh);  sh += eh[i];
    }
    float iw = 1.0f / sw, ih = 1.0f / sh;

    float d[9]; d[0] = 1.0f; d[8] = 1.0f;
    #pragma unroll
    for (int i = 0; i < 7; i++) {
        float u = p[16 + i];
        d[i + 1] = 1e-3f + fmaxf(u, 0.0f) + log1pf(__expf(-fabsf(u)));
    }

    float cumw = 0.0f, cumh = 0.0f, cwl = -TAIL, chl = -TAIL;
    float bcwl = -TAIL, bw = 1.0f, bchl = -TAIL, bh2 = 1.0f, bd0 = 1.0f, bd1 = 1.0f;
    #pragma unroll
    for (int i = 0; i < 8; i++) {
        cumw += 1e-3f + 0.992f * (ew[i] * iw);
        cumh += 1e-3f + 0.992f * (eh[i] * ih);
        float cwr = (i == 7) ? TAIL : fmaf(2.0f * TAIL, cumw, -TAIL);
        float chr = (i == 7) ? TAIL : fmaf(2.0f * TAIL, cumh, -TAIL);
        if (xc >= cwl) { bcwl = cwl; bw = cwr - cwl; bchl = chl; bh2 = chr - chl; bd0 = d[i]; bd1 = d[i + 1]; }
        cwl = cwr; chl = chr;
    }

    float th  = (xc - bcwl) / bw;
    float th1 = th * (1.0f - th);
    float dl  = bh2 / bw;
    float den = dl + (bd0 + bd1 - 2.0f * dl) * th1;
    float y   = bchl + bh2 * (dl * th * th + bd0 * th1) / den;
    float omt = 1.0f - th;
    float ln  = dl * dl * (bd1 * th * th + 2.0f * dl * th1 + bd0 * omt * omt);
    float lad = __logf(ln) - 2.0f * __logf(den);
    float2 r; r.x = inside ? y : x; r.y = inside ? lad : 0.0f;
    return r;
}

// ---------------- main fused kernel ----------------
__global__ void __launch_bounds__(NTHR, 2)
maf_kernel(const float* __restrict__ x, const float* __restrict__ cond,
           const float* __restrict__ bh, const float* __restrict__ bf,
           float* __restrict__ out)
{
    extern __shared__ char smc[];
    float*  z32  = (float*)(smc + OB_Z32);   // [64][49]
    __half* z16  = (__half*)(smc + OB_Z16);  // [64][72]
    float*  ld_s = (float*)(smc + OB_LD);    // [64]
    __half* act  = (__half*)(smc + OB_ACT);  // [64][264]
    __half* par  = (__half*)(smc + OB_PAR);  // [64][202]

    const int tid  = threadIdx.x;
    const int row0 = blockIdx.x * MROWS;

    for (int i = tid; i < MROWS * DF; i += NTHR) {
        int r = i / DF, f = i - r * DF;
        z32[r * Z32S + f] = x[(row0 + r) * DF + f];
    }
    for (int i = tid; i < MROWS * 64; i += NTHR) {
        int r = i >> 6, f = i & 63;
        float v = (f < DF) ? x[(row0 + r) * DF + f]
                 : (f == 45) ? cond[row0 + r]
                 : (f == 46) ? 1.0f : 0.0f;
        z16[r * Z16S + acol(f)] = __float2half(v);
    }
    if (tid < MROWS) ld_s[tid] = 0.0f;
    // ordering via dense entry barrier

    for (int b = 0; b < NBLK; b++) {
        dense<2, false, false>(g_W0p + (size_t)b * 2 * 256 * 32, nullptr,
                               z16, Z16S, act, tid);
        dense<8, true, true>(g_Whp + (size_t)(b * 2 + 0) * 8 * 256 * 32, bh + (b * 2 + 0) * 256,
                             act, AS16, act, tid);
        dense<8, true, true>(g_Whp + (size_t)(b * 2 + 1) * 8 * 256 * 32, bh + (b * 2 + 1) * 256,
                             act, AS16, act, tid);

        for (int ch = 0; ch < NCHK; ch++) {
            f_chunk(g_Wfp + (size_t)(b * NCHK + ch) * 8 * FN * 32, act, par, tid);
            __syncthreads();   // par epilogue visible before spline reads
            {
                int r = tid & 63, flb = tid >> 6;   // flb 0..3; handle flb and flb+4
                float lsum = 0.0f;
                #pragma unroll
                for (int q = 0; q < 2; q++) {
                    int fl = flb + q * 4;
                    int f = ch * 8 + fl;
                    if (f < DF) {
                        float p[23];
                        const float* bfp = bf + b * DM + f * 23;
                        const __half* pp = par + r * PSTR + fl * 24;
                        #pragma unroll
                        for (int i = 0; i < 23; i++)
                            p[i] = __half2float(pp[i]) + bfp[i];
                        float xv = z32[r * Z32S + f];
                        float2 yr = rq_spline(p, xv);
                        z32[r * Z32S + f] = yr.x;
                        z16[r * Z16S + acol(f)] = __float2half(yr.x);
                        lsum += yr.y;
                    }
                }
                if (lsum != 0.0f) atomicAdd(&ld_s[r], lsum);
            }
            // next f_chunk/dense entry barrier orders par reuse and z16 reads
        }
    }

    __syncthreads();
    if (tid < MROWS) {
        float s = 0.0f;
        #pragma unroll
        for (int f = 0; f < DF; f++) { float v = z32[tid * Z32S + f]; s = fmaf(v, v, s); }
        out[row0 + tid] = -0.5f * s - 41.35223399420827f + ld_s[tid];
    }
}

// ---------------- launch ----------------
extern "C" void kernel_launch(void* const* d_in, const int* in_sizes, int n_in,
                              void* d_out, int out_size) {
    const float* x    = (const float*)d_in[0];
    const float* cond = (const float*)d_in[1];
    const float* W0   = (const float*)d_in[2];
    const float* b0   = (const float*)d_in[3];
    const float* Wc   = (const float*)d_in[4];
    const float* bc   = (const float*)d_in[5];
    const float* Wh   = (const float*)d_in[6];
    const float* bh   = (const float*)d_in[7];
    const float* Wf   = (const float*)d_in[8];
    const float* bf   = (const float*)d_in[9];
    float* out = (float*)d_out;
    const int B = in_sizes[0] / DF;

    prep_w0<<<(NBLK * 2 * 256 * 32 + 255) / 256, 256>>>(W0, Wc, b0, bc);
    prep_wh<<<(NBLK * 2 * 8 * 256 * 32 + 255) / 256, 256>>>(Wh);
    prep_wf<<<(NBLK * NCHK * 8 * FN * 32 + 255) / 256, 256>>>(Wf);

    cudaFuncSetAttribute(maf_kernel, cudaFuncAttributeMaxDynamicSharedMemorySize, SMEM_BYTES);
    maf_kernel<<<B / MROWS, NTHR, SMEM_BYTES>>>(x, cond, bh, bf, out);
}

// round 11
// speedup vs baseline: 11.7939x; 1.0424x over previous
#include <cuda_runtime.h>
#include <cuda_fp16.h>

// ---------------- problem constants ----------------
#define NBLK 6
#define DF   45
#define DM   1035
#define MROWS 64           // rows per CTA
#define NTHR 256

#define Z32S 49            // fp32 z row stride
#define Z16S 72            // fp16 z row stride (halves), 64 cols (2 k-slabs)
#define AS16 264           // fp16 act row stride (halves), 256 cols (8 k-slabs)
#define FN   192           // f-chunk cols (8 features x 24)
#define NCHK 6             // f chunks
#define PSTR 194           // fp32 params row stride (floats)

// smem byte offsets (total 105472 -> 2 CTAs/SM)
#define OB_Z32 0
#define OB_Z16 12544                  // 64*49*4
#define OB_LD  (OB_Z16 + 9216)        // 64*72*2
#define OB_ACT (OB_LD + 256)
#define OB_PAR (OB_ACT + 33792)       // 64*264*2
#define SMEM_BYTES (OB_PAR + 49664)   // 64*194*4 -> 105472

// per-N-tile k-slab bounds (degree-sorted hidden): SL[j] nibble-packed
#define SL_PACK 0x88665332u
// per-f-chunk k-slab bounds {2,3,5,6,8,8}
#define FSL_PACK 0x00886532u

// ---------------- device weight images (masked, permuted, k-interleaved, LDG-fragment layout) ----------------
__device__ __half g_W0p[NBLK * 2 * 256 * 32];
__device__ __half g_Whp[NBLK * 2 * 8 * 256 * 32];
__device__ __half g_Wfp[NBLK * NCHK * 8 * FN * 32];
__device__ float  g_bhp[NBLK * 2 * 256];     // degree-permuted hidden biases

// ---------------- helpers ----------------
__device__ __forceinline__ void mma16(float* d, unsigned a0, unsigned a1, unsigned a2, unsigned a3,
                                      unsigned b0, unsigned b1) {
    asm volatile("mma.sync.aligned.m16n8k16.row.col.f32.f16.f16.f32 "
        "{%0,%1,%2,%3},{%4,%5,%6,%7},{%8,%9},{%0,%1,%2,%3};"
        : "+f"(d[0]), "+f"(d[1]), "+f"(d[2]), "+f"(d[3])
        : "r"(a0), "r"(a1), "r"(a2), "r"(a3), "r"(b0), "r"(b1));
}
// phys column of logical k within interleaved 32-k slabs (A-side layout)
__device__ __forceinline__ int acol(int c) {
    int s = c >> 5, k32 = c & 31, step = k32 >> 4, w16 = k32 & 15;
    int hi = w16 >> 3, t = (w16 & 7) >> 1, q = hi * 2 + (w16 & 1);
    return s * 32 + t * 8 + step * 4 + q;
}
// logical k from slab s, phys pos p (<32)
__device__ __forceinline__ int kfp2(int s, int p) {
    int t = p >> 3, rem = p & 7, step = rem >> 2, q = rem & 3;
    int w16 = (q < 2) ? (2 * t + q) : (8 + 2 * t + (q - 2));
    return s * 32 + step * 16 + w16;
}
// degree-sort inverse: original hidden unit for sorted index j
// degrees d=h%44; counts: 6 for d<36, 5 for d>=36; stable by h
__device__ __forceinline__ int invp(int j) {
    return (j < 216) ? (j / 6 + 44 * (j % 6))
                     : (36 + (j - 216) / 5 + 44 * ((j - 216) % 5));
}

// ---------------- prep kernels ----------------
__global__ void prep_w0(const float* __restrict__ W0, const float* __restrict__ Wc,
                        const float* __restrict__ b0, const float* __restrict__ bc) {
    int idx = blockIdx.x * blockDim.x + threadIdx.x;
    if (idx >= NBLK * 2 * 256 * 32) return;
    int p = idx & 31, n = (idx >> 5) & 255, s = (idx >> 13) & 1, b = idx >> 14;
    int k = kfp2(s, p);
    int o = invp(n);
    float v = 0.0f;
    if (k < DF)       v = ((o % 44) >= k) ? W0[(b * 256 + o) * DF + k] : 0.0f;
    else if (k == 45) v = Wc[b * 256 + o];
    else if (k == 46) v = b0[b * 256 + o] + bc[b * 256 + o];
    g_W0p[idx] = __float2half(v);
}
__global__ void prep_wh(const float* __restrict__ Wh) {
    int idx = blockIdx.x * blockDim.x + threadIdx.x;
    if (idx >= NBLK * 2 * 8 * 256 * 32) return;
    int p = idx & 31, n = (idx >> 5) & 255, s = (idx >> 13) & 7, bl = idx >> 16;
    int o = invp(n);
    int kk = invp(kfp2(s, p));
    float v = ((o % 44) >= (kk % 44)) ? Wh[((size_t)(bl * 256 + o)) * 256 + kk] : 0.0f;
    g_Whp[idx] = __float2half(v);
}
__global__ void prep_wf(const float* __restrict__ Wf) {
    int idx = blockIdx.x * blockDim.x + threadIdx.x;
    if (idx >= NBLK * NCHK * 8 * FN * 32) return;
    int p = idx & 31, n = (idx >> 5) % FN, s = (idx / (FN * 32)) & 7;
    int ch = (idx / (FN * 32 * 8)) % NCHK, b = idx / (FN * 32 * 8 * NCHK);
    int kk = invp(kfp2(s, p));
    int fl = n / 24, i = n % 24, f = ch * 8 + fl;
    float v = 0.0f;
    if (i < 23 && f < DF && f > (kk % 44))
        v = Wf[((size_t)(b * DM + f * 23 + i)) * 256 + kk];
    g_Wfp[idx] = __float2half(v);
}
__global__ void prep_bh(const float* __restrict__ bh) {
    int idx = blockIdx.x * blockDim.x + threadIdx.x;
    if (idx >= NBLK * 2 * 256) return;
    int n = idx & 255, bl = idx >> 8;
    g_bhp[idx] = bh[bl * 256 + invp(n)];
}

// ---------------- L0 dense: [64 x 256] = z16[64 x 64] * W0[64 x 256] (no bias/relu; bias folded) ----------------
__device__ __forceinline__ void dense0(const __half* __restrict__ Wg,
                                       const __half* __restrict__ z16,
                                       __half* __restrict__ dst, int tid)
{
    const int lane = tid & 31, w = tid >> 5;
    const int wm = w & 1, wn = w >> 1, g = lane >> 2, t = lane & 3;

    float acc[2][8][4];
    #pragma unroll
    for (int mt = 0; mt < 2; mt++)
        #pragma unroll
        for (int nt = 0; nt < 8; nt++)
            acc[mt][nt][0] = acc[mt][nt][1] = acc[mt][nt][2] = acc[mt][nt][3] = 0.0f;

    __syncthreads();   // entry: spline writers of z16 / prior readers of dst arrived

    const __half* aprow = z16 + (wm * 32 + g) * Z16S + t * 8;
    const __half* bbase = Wg + ((size_t)(wn * 64 + g)) * 32 + t * 8;

    #pragma unroll
    for (int s = 0; s < 2; s++) {
        uint4 Av[4];
        {
            const __half* ap = aprow + s * 32;
            Av[0] = *(const uint4*)ap;
            Av[1] = *(const uint4*)(ap + 8 * Z16S);
            Av[2] = *(const uint4*)(ap + 16 * Z16S);
            Av[3] = *(const uint4*)(ap + 24 * Z16S);
        }
        const __half* bp = bbase + (size_t)s * (256 * 32);
        #pragma unroll
        for (int nt = 0; nt < 8; nt++) {
            uint4 Bv = *(const uint4*)(bp + nt * (8 * 32));
            mma16(acc[0][nt], Av[0].x, Av[1].x, Av[0].y, Av[1].y, Bv.x, Bv.y);
            mma16(acc[1][nt], Av[2].x, Av[3].x, Av[2].y, Av[3].y, Bv.x, Bv.y);
            mma16(acc[0][nt], Av[0].z, Av[1].z, Av[0].w, Av[1].w, Bv.z, Bv.w);
            mma16(acc[1][nt], Av[2].z, Av[3].z, Av[2].w, Av[3].w, Bv.z, Bv.w);
        }
    }
    #pragma unroll
    for (int nt = 0; nt < 8; nt++) {
        int c0 = wn * 64 + nt * 8 + 2 * t;
        int pos = acol(c0);
        #pragma unroll
        for (int mt = 0; mt < 2; mt++) {
            int r0 = wm * 32 + mt * 16 + g;
            *(half2*)(dst + r0 * AS16 + pos)       = __floats2half2_rn(acc[mt][nt][0], acc[mt][nt][1]);
            *(half2*)(dst + (r0 + 8) * AS16 + pos) = __floats2half2_rn(acc[mt][nt][2], acc[mt][nt][3]);
        }
    }
}

// ---------------- hidden dense (degree-sorted, per-warp truncated K): in-place on act ----------------
// 8 warps: wm = w&1 (2 x 32 rows), wj = w>>1 handles 32-col tiles {wj, 7-wj}
__device__ __forceinline__ void hidden_dense(const __half* __restrict__ Wg,
                                             const float* __restrict__ biasP,
                                             __half* __restrict__ act, int tid)
{
    const int lane = tid & 31, w = tid >> 5;
    const int wm = w & 1, wj = w >> 1, g = lane >> 2, t = lane & 3;

    float acc[2][2][4][4];
    #pragma unroll
    for (int ti = 0; ti < 2; ti++)
        #pragma unroll
        for (int mt = 0; mt < 2; mt++)
            #pragma unroll
            for (int j = 0; j < 4; j++)
                acc[ti][mt][j][0] = acc[ti][mt][j][1] = acc[ti][mt][j][2] = acc[ti][mt][j][3] = 0.0f;

    __syncthreads();   // entry

    const __half* aprow = act + (wm * 32 + g) * AS16 + t * 8;

    #pragma unroll
    for (int ti = 0; ti < 2; ti++) {
        const int tile = ti ? (7 - wj) : wj;
        const int ns = (int)((SL_PACK >> (4 * tile)) & 0xFu);
        const __half* bbase = Wg + ((size_t)(tile * 32 + g)) * 32 + t * 8;
        for (int s = 0; s < ns; s++) {
            uint4 Av[4];
            {
                const __half* ap = aprow + s * 32;
                Av[0] = *(const uint4*)ap;
                Av[1] = *(const uint4*)(ap + 8 * AS16);
                Av[2] = *(const uint4*)(ap + 16 * AS16);
                Av[3] = *(const uint4*)(ap + 24 * AS16);
            }
            const __half* bp = bbase + (size_t)s * (256 * 32);
            #pragma unroll
            for (int j = 0; j < 4; j++) {
                uint4 Bv = *(const uint4*)(bp + j * (8 * 32));
                mma16(acc[ti][0][j], Av[0].x, Av[1].x, Av[0].y, Av[1].y, Bv.x, Bv.y);
                mma16(acc[ti][1][j], Av[2].x, Av[3].x, Av[2].y, Av[3].y, Bv.x, Bv.y);
                mma16(acc[ti][0][j], Av[0].z, Av[1].z, Av[0].w, Av[1].w, Bv.z, Bv.w);
                mma16(acc[ti][1][j], Av[2].z, Av[3].z, Av[2].w, Av[3].w, Bv.z, Bv.w);
            }
        }
    }
    __syncthreads();   // all A reads complete -> in-place overwrite safe
    #pragma unroll
    for (int ti = 0; ti < 2; ti++) {
        const int tile = ti ? (7 - wj) : wj;
        #pragma unroll
        for (int j = 0; j < 4; j++) {
            int c0 = tile * 32 + j * 8 + 2 * t;
            int pos = acol(c0);
            float2 bb = *(const float2*)(biasP + c0);
            #pragma unroll
            for (int mt = 0; mt < 2; mt++) {
                int r0 = wm * 32 + mt * 16 + g;
                float v0 = fmaxf(acc[ti][mt][j][0] + bb.x, 0.0f);
                float v1 = fmaxf(acc[ti][mt][j][1] + bb.y, 0.0f);
                float v2 = fmaxf(acc[ti][mt][j][2] + bb.x, 0.0f);
                float v3 = fmaxf(acc[ti][mt][j][3] + bb.y, 0.0f);
                *(half2*)(act + r0 * AS16 + pos)       = __floats2half2_rn(v0, v1);
                *(half2*)(act + (r0 + 8) * AS16 + pos) = __floats2half2_rn(v2, v3);
            }
        }
    }
}

// ---------------- f-layer chunk: [64 x 192] = act[64 x K(ns*32)] * Wf ----------------
// 8 warps: wm = w&1, wn = w>>1 (4 x 48 cols); warp-uniform truncated K
__device__ __forceinline__ void f_chunk(const __half* __restrict__ Wg,
                                        const __half* __restrict__ act,
                                        float* __restrict__ par, int ns, int tid)
{
    const int lane = tid & 31, w = tid >> 5;
    const int wm = w & 1, wn = w >> 1, g = lane >> 2, t = lane & 3;

    float acc[2][6][4];
    #pragma unroll
    for (int mt = 0; mt < 2; mt++)
        #pragma unroll
        for (int nt = 0; nt < 6; nt++)
            acc[mt][nt][0] = acc[mt][nt][1] = acc[mt][nt][2] = acc[mt][nt][3] = 0.0f;

    __syncthreads();   // entry: previous spline readers of par arrived

    const __half* aprow = act + (wm * 32 + g) * AS16 + t * 8;
    const __half* bbase = Wg + ((size_t)(wn * 48 + g)) * 32 + t * 8;

    for (int s = 0; s < ns; s++) {
        uint4 Av[4];
        {
            const __half* ap = aprow + s * 32;
            Av[0] = *(const uint4*)ap;
            Av[1] = *(const uint4*)(ap + 8 * AS16);
            Av[2] = *(const uint4*)(ap + 16 * AS16);
            Av[3] = *(const uint4*)(ap + 24 * AS16);
        }
        const __half* bp = bbase + (size_t)s * (FN * 32);
        #pragma unroll
        for (int nt = 0; nt < 6; nt++) {
            uint4 Bv = *(const uint4*)(bp + nt * (8 * 32));
            mma16(acc[0][nt], Av[0].x, Av[1].x, Av[0].y, Av[1].y, Bv.x, Bv.y);
            mma16(acc[1][nt], Av[2].x, Av[3].x, Av[2].y, Av[3].y, Bv.x, Bv.y);
            mma16(acc[0][nt], Av[0].z, Av[1].z, Av[0].w, Av[1].w, Bv.z, Bv.w);
            mma16(acc[1][nt], Av[2].z, Av[3].z, Av[2].w, Av[3].w, Bv.z, Bv.w);
        }
    }
    #pragma unroll
    for (int nt = 0; nt < 6; nt++) {
        int c0 = wn * 48 + nt * 8 + 2 * t;
        #pragma unroll
        for (int mt = 0; mt < 2; mt++) {
            int r0 = wm * 32 + mt * 16 + g;
            *(float2*)(par + r0 * PSTR + c0)       = make_float2(acc[mt][nt][0], acc[mt][nt][1]);
            *(float2*)(par + (r0 + 8) * PSTR + c0) = make_float2(acc[mt][nt][2], acc[mt][nt][3]);
        }
    }
}

// ---------------- rational-quadratic spline, K=8 bins (no softmax max-shift: args are tiny) ----------------
__device__ __forceinline__ float2 rq_spline(const float* __restrict__ p, float x)
{
    const float TAIL = 13.815510557964274f;
    const float INVS = 0.0625f;
    bool inside = (x >= -TAIL) && (x <= TAIL);
    float xc = fminf(fmaxf(x, -TAIL), TAIL);

    float ew[8], eh[8];
    float sw = 0.0f, sh = 0.0f;
    #pragma unroll
    for (int i = 0; i < 8; i++) {
        ew[i] = __expf(p[i] * INVS);      sw += ew[i];
        eh[i] = __expf(p[8 + i] * INVS);  sh += eh[i];
    }
    float iw = 1.0f / sw, ih = 1.0f / sh;

    float d[9]; d[0] = 1.0f; d[8] = 1.0f;
    #pragma unroll
    for (int i = 0; i < 7; i++) {
        float u = p[16 + i];
        d[i + 1] = 1e-3f + fmaxf(u, 0.0f) + log1pf(__expf(-fabsf(u)));
    }

    float cumw = 0.0f, cumh = 0.0f, cwl = -TAIL, chl = -TAIL;
    float bcwl = -TAIL, bw = 1.0f, bchl = -TAIL, bh2 = 1.0f, bd0 = 1.0f, bd1 = 1.0f;
    #pragma unroll
    for (int i = 0; i < 8; i++) {
        cumw += 1e-3f + 0.992f * (ew[i] * iw);
        cumh += 1e-3f + 0.992f * (eh[i] * ih);
        float cwr = (i == 7) ? TAIL : fmaf(2.0f * TAIL, cumw, -TAIL);
        float chr = (i == 7) ? TAIL : fmaf(2.0f * TAIL, cumh, -TAIL);
        if (xc >= cwl) { bcwl = cwl; bw = cwr - cwl; bchl = chl; bh2 = chr - chl; bd0 = d[i]; bd1 = d[i + 1]; }
        cwl = cwr; chl = chr;
    }

    float th  = (xc - bcwl) / bw;
    float th1 = th * (1.0f - th);
    float dl  = bh2 / bw;
    float den = dl + (bd0 + bd1 - 2.0f * dl) * th1;
    float y   = bchl + bh2 * (dl * th * th + bd0 * th1) / den;
    float omt = 1.0f - th;
    float ln  = dl * dl * (bd1 * th * th + 2.0f * dl * th1 + bd0 * omt * omt);
    float lad = __logf(ln) - 2.0f * __logf(den);
    float2 r; r.x = inside ? y : x; r.y = inside ? lad : 0.0f;
    return r;
}

// ---------------- main fused kernel ----------------
__global__ void __launch_bounds__(NTHR, 2)
maf_kernel(const float* __restrict__ x, const float* __restrict__ cond,
           const float* __restrict__ bf,
           float* __restrict__ out)
{
    extern __shared__ char smc[];
    float*  z32  = (float*)(smc + OB_Z32);   // [64][49]
    __half* z16  = (__half*)(smc + OB_Z16);  // [64][72]
    float*  ld_s = (float*)(smc + OB_LD);    // [64]
    __half* act  = (__half*)(smc + OB_ACT);  // [64][264]
    float*  par  = (float*)(smc + OB_PAR);   // [64][194]

    const int tid  = threadIdx.x;
    const int row0 = blockIdx.x * MROWS;

    for (int i = tid; i < MROWS * DF; i += NTHR) {
        int r = i / DF, f = i - r * DF;
        z32[r * Z32S + f] = x[(row0 + r) * DF + f];
    }
    for (int i = tid; i < MROWS * 64; i += NTHR) {
        int r = i >> 6, f = i & 63;
        float v = (f < DF) ? x[(row0 + r) * DF + f]
                 : (f == 45) ? cond[row0 + r]
                 : (f == 46) ? 1.0f : 0.0f;
        z16[r * Z16S + acol(f)] = __float2half(v);
    }
    if (tid < MROWS) ld_s[tid] = 0.0f;
    // ordering via dense0 entry barrier

    for (int b = 0; b < NBLK; b++) {
        dense0(g_W0p + (size_t)b * 2 * 256 * 32, z16, act, tid);
        hidden_dense(g_Whp + (size_t)(b * 2 + 0) * 8 * 256 * 32, g_bhp + (b * 2 + 0) * 256, act, tid);
        hidden_dense(g_Whp + (size_t)(b * 2 + 1) * 8 * 256 * 32, g_bhp + (b * 2 + 1) * 256, act, tid);

        for (int ch = 0; ch < NCHK; ch++) {
            int ns = (int)((FSL_PACK >> (4 * ch)) & 0xFu);
            f_chunk(g_Wfp + (size_t)(b * NCHK + ch) * 8 * FN * 32, act, par, ns, tid);
            __syncthreads();   // par epilogue visible before spline reads
            {
                int r = tid & 63, flb = tid >> 6;   // flb 0..3; handle flb and flb+4
                float lsum = 0.0f;
                #pragma unroll
                for (int q = 0; q < 2; q++) {
                    int fl = flb + q * 4;
                    int f = ch * 8 + fl;
                    if (f < DF) {
                        float p[23];
                        const float* bfp = bf + b * DM + f * 23;
                        const float* pp = par + r * PSTR + fl * 24;
                        #pragma unroll
                        for (int i = 0; i < 23; i++)
                            p[i] = pp[i] + bfp[i];
                        float xv = z32[r * Z32S + f];
                        float2 yr = rq_spline(p, xv);
                        z32[r * Z32S + f] = yr.x;
                        z16[r * Z16S + acol(f)] = __float2half(yr.x);
                        lsum += yr.y;
                    }
                }
                if (lsum != 0.0f) atomicAdd(&ld_s[r], lsum);
            }
            // next f_chunk/dense0 entry barrier orders par reuse and z16 reads
        }
    }

    __syncthreads();
    if (tid < MROWS) {
        float s = 0.0f;
        #pragma unroll
        for (int f = 0; f < DF; f++) { float v = z32[tid * Z32S + f]; s = fmaf(v, v, s); }
        out[row0 + tid] = -0.5f * s - 41.35223399420827f + ld_s[tid];
    }
}

// ---------------- launch ----------------
extern "C" void kernel_launch(void* const* d_in, const int* in_sizes, int n_in,
                              void* d_out, int out_size) {
    const float* x    = (const float*)d_in[0];
    const float* cond = (const float*)d_in[1];
    const float* W0   = (const float*)d_in[2];
    const float* b0   = (const float*)d_in[3];
    const float* Wc   = (const float*)d_in[4];
    const float* bc   = (const float*)d_in[5];
    const float* Wh   = (const float*)d_in[6];
    const float* bh   = (const float*)d_in[7];
    const float* Wf   = (const float*)d_in[8];
    const float* bf   = (const float*)d_in[9];
    float* out = (float*)d_out;
    const int B = in_sizes[0] / DF;

    prep_w0<<<(NBLK * 2 * 256 * 32 + 255) / 256, 256>>>(W0, Wc, b0, bc);
    prep_wh<<<(NBLK * 2 * 8 * 256 * 32 + 255) / 256, 256>>>(Wh);
    prep_wf<<<(NBLK * NCHK * 8 * FN * 32 + 255) / 256, 256>>>(Wf);
    prep_bh<<<(NBLK * 2 * 256 + 255) / 256, 256>>>(bh);

    cudaFuncSetAttribute(maf_kernel, cudaFuncAttributeMaxDynamicSharedMemorySize, SMEM_BYTES);
    maf_kernel<<<B / MROWS, NTHR, SMEM_BYTES>>>(x, cond, bf, out);
}

// round 12
// speedup vs baseline: 13.2865x; 1.1266x over previous
#include <cuda_runtime.h>
#include <cuda_fp16.h>

// ---------------- problem constants ----------------
#define NBLK 6
#define DF   45
#define DM   1035
#define MROWS 64           // rows per CTA
#define NTHR 256

#define Z32S 49            // fp32 z row stride
#define Z16S 72            // fp16 z row stride (halves), 64 cols (2 k-slabs)
#define AS16 264           // fp16 act row stride (halves), 256 cols (8 k-slabs)
#define FN   192           // f-chunk cols (8 features x 24)
#define NCHK 6             // f chunks
#define PSTR 202           // fp16 params row stride (halves)

// smem byte offsets (total 108288 -> 2 CTAs/SM)
#define OB_Z32  0
#define OB_Z16  12544                 // 64*49*4
#define OB_LDP  (OB_Z16 + 9216)       // 64*72*2 -> ld partials [256]
#define OB_ACTA (OB_LDP + 1024)
#define OB_REGN (OB_ACTA + 33792)     // overlap region: actB (33792) OR parA/parB (2*25856)
#define SMEM_BYTES (OB_REGN + 51712)  // 108288

// per-N-tile k-slab bounds (degree-sorted hidden): SL[j] nibble-packed
#define SL_PACK 0x88665332u
// per-f-chunk k-slab bounds {2,3,5,6,8,8}
#define FSL_PACK 0x00886532u

// ---------------- device weight images (masked, permuted, k-interleaved, LDG-fragment layout) ----------------
__device__ __half g_W0p[NBLK * 2 * 256 * 32];
__device__ __half g_Whp[NBLK * 2 * 8 * 256 * 32];
__device__ __half g_Wfp[NBLK * NCHK * 8 * FN * 32];
__device__ float  g_bhp[NBLK * 2 * 256];     // degree-permuted hidden biases

// ---------------- helpers ----------------
__device__ __forceinline__ void mma16(float* d, unsigned a0, unsigned a1, unsigned a2, unsigned a3,
                                      unsigned b0, unsigned b1) {
    asm volatile("mma.sync.aligned.m16n8k16.row.col.f32.f16.f16.f32 "
        "{%0,%1,%2,%3},{%4,%5,%6,%7},{%8,%9},{%0,%1,%2,%3};"
        : "+f"(d[0]), "+f"(d[1]), "+f"(d[2]), "+f"(d[3])
        : "r"(a0), "r"(a1), "r"(a2), "r"(a3), "r"(b0), "r"(b1));
}
// phys column of logical k within interleaved 32-k slabs (A-side layout)
__device__ __forceinline__ int acol(int c) {
    int s = c >> 5, k32 = c & 31, step = k32 >> 4, w16 = k32 & 15;
    int hi = w16 >> 3, t = (w16 & 7) >> 1, q = hi * 2 + (w16 & 1);
    return s * 32 + t * 8 + step * 4 + q;
}
// logical k from slab s, phys pos p (<32)
__device__ __forceinline__ int kfp2(int s, int p) {
    int t = p >> 3, rem = p & 7, step = rem >> 2, q = rem & 3;
    int w16 = (q < 2) ? (2 * t + q) : (8 + 2 * t + (q - 2));
    return s * 32 + step * 16 + w16;
}
// degree-sort inverse: original hidden unit for sorted index j
__device__ __forceinline__ int invp(int j) {
    return (j < 216) ? (j / 6 + 44 * (j % 6))
                     : (36 + (j - 216) / 5 + 44 * ((j - 216) % 5));
}

// ---------------- prep kernels ----------------
__global__ void prep_w0(const float* __restrict__ W0, const float* __restrict__ Wc,
                        const float* __restrict__ b0, const float* __restrict__ bc) {
    int idx = blockIdx.x * blockDim.x + threadIdx.x;
    if (idx >= NBLK * 2 * 256 * 32) return;
    int p = idx & 31, n = (idx >> 5) & 255, s = (idx >> 13) & 1, b = idx >> 14;
    int k = kfp2(s, p);
    int o = invp(n);
    float v = 0.0f;
    if (k < DF)       v = ((o % 44) >= k) ? W0[(b * 256 + o) * DF + k] : 0.0f;
    else if (k == 45) v = Wc[b * 256 + o];
    else if (k == 46) v = b0[b * 256 + o] + bc[b * 256 + o];
    g_W0p[idx] = __float2half(v);
}
__global__ void prep_wh(const float* __restrict__ Wh) {
    int idx = blockIdx.x * blockDim.x + threadIdx.x;
    if (idx >= NBLK * 2 * 8 * 256 * 32) return;
    int p = idx & 31, n = (idx >> 5) & 255, s = (idx >> 13) & 7, bl = idx >> 16;
    int o = invp(n);
    int kk = invp(kfp2(s, p));
    float v = ((o % 44) >= (kk % 44)) ? Wh[((size_t)(bl * 256 + o)) * 256 + kk] : 0.0f;
    g_Whp[idx] = __float2half(v);
}
__global__ void prep_wf(const float* __restrict__ Wf) {
    int idx = blockIdx.x * blockDim.x + threadIdx.x;
    if (idx >= NBLK * NCHK * 8 * FN * 32) return;
    int p = idx & 31, n = (idx >> 5) % FN, s = (idx / (FN * 32)) & 7;
    int ch = (idx / (FN * 32 * 8)) % NCHK, b = idx / (FN * 32 * 8 * NCHK);
    int kk = invp(kfp2(s, p));
    int fl = n / 24, i = n % 24, f = ch * 8 + fl;
    float v = 0.0f;
    if (i < 23 && f < DF && f > (kk % 44))
        v = Wf[((size_t)(b * DM + f * 23 + i)) * 256 + kk];
    g_Wfp[idx] = __float2half(v);
}
__global__ void prep_bh(const float* __restrict__ bh) {
    int idx = blockIdx.x * blockDim.x + threadIdx.x;
    if (idx >= NBLK * 2 * 256) return;
    int n = idx & 255, bl = idx >> 8;
    g_bhp[idx] = bh[bl * 256 + invp(n)];
}

// ---------------- L0 dense: [64 x 256] = z16[64 x 64] * W0[64 x 256] ----------------
__device__ __forceinline__ void dense0(const __half* __restrict__ Wg,
                                       const __half* __restrict__ z16,
                                       __half* __restrict__ dst, int tid)
{
    const int lane = tid & 31, w = tid >> 5;
    const int wm = w & 1, wn = w >> 1, g = lane >> 2, t = lane & 3;

    float acc[2][8][4];
    #pragma unroll
    for (int mt = 0; mt < 2; mt++)
        #pragma unroll
        for (int nt = 0; nt < 8; nt++)
            acc[mt][nt][0] = acc[mt][nt][1] = acc[mt][nt][2] = acc[mt][nt][3] = 0.0f;

    __syncthreads();   // entry: spline z16 writes / prior actA readers arrived

    const __half* aprow = z16 + (wm * 32 + g) * Z16S + t * 8;
    const __half* bbase = Wg + ((size_t)(wn * 64 + g)) * 32 + t * 8;

    #pragma unroll
    for (int s = 0; s < 2; s++) {
        uint4 Av[4];
        {
            const __half* ap = aprow + s * 32;
            Av[0] = *(const uint4*)ap;
            Av[1] = *(const uint4*)(ap + 8 * Z16S);
            Av[2] = *(const uint4*)(ap + 16 * Z16S);
            Av[3] = *(const uint4*)(ap + 24 * Z16S);
        }
        const __half* bp = bbase + (size_t)s * (256 * 32);
        #pragma unroll
        for (int nt = 0; nt < 8; nt++) {
            uint4 Bv = *(const uint4*)(bp + nt * (8 * 32));
            mma16(acc[0][nt], Av[0].x, Av[1].x, Av[0].y, Av[1].y, Bv.x, Bv.y);
            mma16(acc[1][nt], Av[2].x, Av[3].x, Av[2].y, Av[3].y, Bv.x, Bv.y);
            mma16(acc[0][nt], Av[0].z, Av[1].z, Av[0].w, Av[1].w, Bv.z, Bv.w);
            mma16(acc[1][nt], Av[2].z, Av[3].z, Av[2].w, Av[3].w, Bv.z, Bv.w);
        }
    }
    #pragma unroll
    for (int nt = 0; nt < 8; nt++) {
        int c0 = wn * 64 + nt * 8 + 2 * t;
        int pos = acol(c0);
        #pragma unroll
        for (int mt = 0; mt < 2; mt++) {
            int r0 = wm * 32 + mt * 16 + g;
            *(half2*)(dst + r0 * AS16 + pos)       = __floats2half2_rn(acc[mt][nt][0], acc[mt][nt][1]);
            *(half2*)(dst + (r0 + 8) * AS16 + pos) = __floats2half2_rn(acc[mt][nt][2], acc[mt][nt][3]);
        }
    }
}

// ---------------- hidden dense (degree-sorted, per-warp truncated K), OUT-OF-PLACE ----------------
__device__ __forceinline__ void hidden_dense(const __half* __restrict__ Wg,
                                             const float* __restrict__ biasP,
                                             const __half* __restrict__ src,
                                             __half* __restrict__ dst, int tid)
{
    const int lane = tid & 31, w = tid >> 5;
    const int wm = w & 1, wj = w >> 1, g = lane >> 2, t = lane & 3;

    float acc[2][2][4][4];
    #pragma unroll
    for (int ti = 0; ti < 2; ti++)
        #pragma unroll
        for (int mt = 0; mt < 2; mt++)
            #pragma unroll
            for (int j = 0; j < 4; j++)
                acc[ti][mt][j][0] = acc[ti][mt][j][1] = acc[ti][mt][j][2] = acc[ti][mt][j][3] = 0.0f;

    __syncthreads();   // entry: src writers / prior dst readers arrived

    const __half* aprow = src + (wm * 32 + g) * AS16 + t * 8;

    #pragma unroll
    for (int ti = 0; ti < 2; ti++) {
        const int tile = ti ? (7 - wj) : wj;
        const int ns = (int)((SL_PACK >> (4 * tile)) & 0xFu);
        const __half* bbase = Wg + ((size_t)(tile * 32 + g)) * 32 + t * 8;
        for (int s = 0; s < ns; s++) {
            uint4 Av[4];
            {
                const __half* ap = aprow + s * 32;
                Av[0] = *(const uint4*)ap;
                Av[1] = *(const uint4*)(ap + 8 * AS16);
                Av[2] = *(const uint4*)(ap + 16 * AS16);
                Av[3] = *(const uint4*)(ap + 24 * AS16);
            }
            const __half* bp = bbase + (size_t)s * (256 * 32);
            #pragma unroll
            for (int j = 0; j < 4; j++) {
                uint4 Bv = *(const uint4*)(bp + j * (8 * 32));
                mma16(acc[ti][0][j], Av[0].x, Av[1].x, Av[0].y, Av[1].y, Bv.x, Bv.y);
                mma16(acc[ti][1][j], Av[2].x, Av[3].x, Av[2].y, Av[3].y, Bv.x, Bv.y);
                mma16(acc[ti][0][j], Av[0].z, Av[1].z, Av[0].w, Av[1].w, Bv.z, Bv.w);
                mma16(acc[ti][1][j], Av[2].z, Av[3].z, Av[2].w, Av[3].w, Bv.z, Bv.w);
            }
        }
    }
    // no mid barrier: dst != src
    #pragma unroll
    for (int ti = 0; ti < 2; ti++) {
        const int tile = ti ? (7 - wj) : wj;
        #pragma unroll
        for (int j = 0; j < 4; j++) {
            int c0 = tile * 32 + j * 8 + 2 * t;
            int pos = acol(c0);
            float2 bb = *(const float2*)(biasP + c0);
            #pragma unroll
            for (int mt = 0; mt < 2; mt++) {
                int r0 = wm * 32 + mt * 16 + g;
                float v0 = fmaxf(acc[ti][mt][j][0] + bb.x, 0.0f);
                float v1 = fmaxf(acc[ti][mt][j][1] + bb.y, 0.0f);
                float v2 = fmaxf(acc[ti][mt][j][2] + bb.x, 0.0f);
                float v3 = fmaxf(acc[ti][mt][j][3] + bb.y, 0.0f);
                *(half2*)(dst + r0 * AS16 + pos)       = __floats2half2_rn(v0, v1);
                *(half2*)(dst + (r0 + 8) * AS16 + pos) = __floats2half2_rn(v2, v3);
            }
        }
    }
}

// ---------------- f-layer chunk MMA + epilogue (NO barrier inside) ----------------
__device__ __forceinline__ void f_chunk(const __half* __restrict__ Wg,
                                        const __half* __restrict__ act,
                                        __half* __restrict__ par, int ns, int tid)
{
    const int lane = tid & 31, w = tid >> 5;
    const int wm = w & 1, wn = w >> 1, g = lane >> 2, t = lane & 3;

    float acc[2][6][4];
    #pragma unroll
    for (int mt = 0; mt < 2; mt++)
        #pragma unroll
        for (int nt = 0; nt < 6; nt++)
            acc[mt][nt][0] = acc[mt][nt][1] = acc[mt][nt][2] = acc[mt][nt][3] = 0.0f;

    const __half* aprow = act + (wm * 32 + g) * AS16 + t * 8;
    const __half* bbase = Wg + ((size_t)(wn * 48 + g)) * 32 + t * 8;

    for (int s = 0; s < ns; s++) {
        uint4 Av[4];
        {
            const __half* ap = aprow + s * 32;
            Av[0] = *(const uint4*)ap;
            Av[1] = *(const uint4*)(ap + 8 * AS16);
            Av[2] = *(const uint4*)(ap + 16 * AS16);
            Av[3] = *(const uint4*)(ap + 24 * AS16);
        }
        const __half* bp = bbase + (size_t)s * (FN * 32);
        #pragma unroll
        for (int nt = 0; nt < 6; nt++) {
            uint4 Bv = *(const uint4*)(bp + nt * (8 * 32));
            mma16(acc[0][nt], Av[0].x, Av[1].x, Av[0].y, Av[1].y, Bv.x, Bv.y);
            mma16(acc[1][nt], Av[2].x, Av[3].x, Av[2].y, Av[3].y, Bv.x, Bv.y);
            mma16(acc[0][nt], Av[0].z, Av[1].z, Av[0].w, Av[1].w, Bv.z, Bv.w);
            mma16(acc[1][nt], Av[2].z, Av[3].z, Av[2].w, Av[3].w, Bv.z, Bv.w);
        }
    }
    #pragma unroll
    for (int nt = 0; nt < 6; nt++) {
        int c0 = wn * 48 + nt * 8 + 2 * t;
        #pragma unroll
        for (int mt = 0; mt < 2; mt++) {
            int r0 = wm * 32 + mt * 16 + g;
            *(half2*)(par + r0 * PSTR + c0)       = __floats2half2_rn(acc[mt][nt][0], acc[mt][nt][1]);
            *(half2*)(par + (r0 + 8) * PSTR + c0) = __floats2half2_rn(acc[mt][nt][2], acc[mt][nt][3]);
        }
    }
}

// ---------------- rational-quadratic spline, K=8 bins ----------------
__device__ __forceinline__ float2 rq_spline(const float* __restrict__ p, float x)
{
    const float TAIL = 13.815510557964274f;
    const float INVS = 0.0625f;
    bool inside = (x >= -TAIL) && (x <= TAIL);
    float xc = fminf(fmaxf(x, -TAIL), TAIL);

    float ew[8], eh[8];
    float sw = 0.0f, sh = 0.0f;
    #pragma unroll
    for (int i = 0; i < 8; i++) {
        ew[i] = __expf(p[i] * INVS);      sw += ew[i];
        eh[i] = __expf(p[8 + i] * INVS);  sh += eh[i];
    }
    float iw = 1.0f / sw, ih = 1.0f / sh;

    float d[9]; d[0] = 1.0f; d[8] = 1.0f;
    #pragma unroll
    for (int i = 0; i < 7; i++) {
        float u = p[16 + i];
        d[i + 1] = 1e-3f + fmaxf(u, 0.0f) + log1pf(__expf(-fabsf(u)));
    }

    float cumw = 0.0f, cumh = 0.0f, cwl = -TAIL, chl = -TAIL;
    float bcwl = -TAIL, bw = 1.0f, bchl = -TAIL, bh2 = 1.0f, bd0 = 1.0f, bd1 = 1.0f;
    #pragma unroll
    for (int i = 0; i < 8; i++) {
        cumw += 1e-3f + 0.992f * (ew[i] * iw);
        cumh += 1e-3f + 0.992f * (eh[i] * ih);
        float cwr = (i == 7) ? TAIL : fmaf(2.0f * TAIL, cumw, -TAIL);
        float chr = (i == 7) ? TAIL : fmaf(2.0f * TAIL, cumh, -TAIL);
        if (xc >= cwl) { bcwl = cwl; bw = cwr - cwl; bchl = chl; bh2 = chr - chl; bd0 = d[i]; bd1 = d[i + 1]; }
        cwl = cwr; chl = chr;
    }

    float th  = (xc - bcwl) / bw;
    float th1 = th * (1.0f - th);
    float dl  = bh2 / bw;
    float den = dl + (bd0 + bd1 - 2.0f * dl) * th1;
    float y   = bchl + bh2 * (dl * th * th + bd0 * th1) / den;
    float omt = 1.0f - th;
    float ln  = dl * dl * (bd1 * th * th + 2.0f * dl * th1 + bd0 * omt * omt);
    float lad = __logf(ln) - 2.0f * __logf(den);
    float2 r; r.x = inside ? y : x; r.y = inside ? lad : 0.0f;
    return r;
}

// spline pass for one chunk: 2 features per thread; accumulates log-det in reg
__device__ __forceinline__ void do_spline(const float* __restrict__ bf, int b, int ch,
                                          const __half* __restrict__ par,
                                          float* __restrict__ z32, __half* __restrict__ z16,
                                          int tid, float& ldacc)
{
    int r = tid & 63, flb = tid >> 6;
    #pragma unroll
    for (int q = 0; q < 2; q++) {
        int fl = flb + q * 4;
        int f = ch * 8 + fl;
        if (f < DF) {
            float p[23];
            const float* bfp = bf + b * DM + f * 23;
            const __half* pp = par + r * PSTR + fl * 24;
            #pragma unroll
            for (int i = 0; i < 23; i++)
                p[i] = __half2float(pp[i]) + bfp[i];
            float xv = z32[r * Z32S + f];
            float2 yr = rq_spline(p, xv);
            z32[r * Z32S + f] = yr.x;
            z16[r * Z16S + acol(f)] = __float2half(yr.x);
            ldacc += yr.y;
        }
    }
}

// ---------------- main fused kernel ----------------
__global__ void __launch_bounds__(NTHR, 2)
maf_kernel(const float* __restrict__ x, const float* __restrict__ cond,
           const float* __restrict__ bf,
           float* __restrict__ out)
{
    extern __shared__ char smc[];
    float*  z32  = (float*)(smc + OB_Z32);    // [64][49]
    __half* z16  = (__half*)(smc + OB_Z16);   // [64][72]
    float*  ldp  = (float*)(smc + OB_LDP);    // [256]
    __half* actA = (__half*)(smc + OB_ACTA);  // [64][264]
    __half* actB = (__half*)(smc + OB_REGN);  // [64][264]   (dead outside hidden phase)
    __half* par0 = (__half*)(smc + OB_REGN);           // [64][202]
    __half* par1 = (__half*)(smc + OB_REGN + 25856);   // [64][202]

    const int tid  = threadIdx.x;
    const int row0 = blockIdx.x * MROWS;
    float ldacc = 0.0f;

    for (int i = tid; i < MROWS * DF; i += NTHR) {
        int r = i / DF, f = i - r * DF;
        z32[r * Z32S + f] = x[(row0 + r) * DF + f];
    }
    for (int i = tid; i < MROWS * 64; i += NTHR) {
        int r = i >> 6, f = i & 63;
        float v = (f < DF) ? x[(row0 + r) * DF + f]
                 : (f == 45) ? cond[row0 + r]
                 : (f == 46) ? 1.0f : 0.0f;
        z16[r * Z16S + acol(f)] = __float2half(v);
    }
    // ordering via dense0 entry barrier

    for (int b = 0; b < NBLK; b++) {
        dense0(g_W0p + (size_t)b * 2 * 256 * 32, z16, actA, tid);
        hidden_dense(g_Whp + (size_t)(b * 2 + 0) * 8 * 256 * 32, g_bhp + (b * 2 + 0) * 256,
                     actA, actB, tid);
        hidden_dense(g_Whp + (size_t)(b * 2 + 1) * 8 * 256 * 32, g_bhp + (b * 2 + 1) * 256,
                     actB, actA, tid);

        const __half* Wfb = g_Wfp + (size_t)(b * NCHK) * 8 * FN * 32;
        for (int ch = 0; ch < NCHK; ch++) {
            __syncthreads();   // ch=0: orders actB reads + actA writes; ch>0: orders par epilogue + prior spline par reads
            __half* parw = (ch & 1) ? par1 : par0;
            int ns = (int)((FSL_PACK >> (4 * ch)) & 0xFu);
            f_chunk(Wfb + (size_t)ch * 8 * FN * 32, actA, parw, ns, tid);
            if (ch > 0)
                do_spline(bf, b, ch - 1, (ch & 1) ? par0 : par1, z32, z16, tid, ldacc);
        }
        __syncthreads();       // chunk 5 epilogue visible
        do_spline(bf, b, NCHK - 1, par1, z32, z16, tid, ldacc);
    }

    ldp[tid] = ldacc;          // tid = flb*64 + r exactly
    __syncthreads();
    if (tid < MROWS) {
        float ld = ldp[tid] + ldp[tid + 64] + ldp[tid + 128] + ldp[tid + 192];
        float s = 0.0f;
        #pragma unroll
        for (int f = 0; f < DF; f++) { float v = z32[tid * Z32S + f]; s = fmaf(v, v, s); }
        out[row0 + tid] = -0.5f * s - 41.35223399420827f + ld;
    }
}

// ---------------- launch ----------------
extern "C" void kernel_launch(void* const* d_in, const int* in_sizes, int n_in,
                              void* d_out, int out_size) {
    const float* x    = (const float*)d_in[0];
    const float* cond = (const float*)d_in[1];
    const float* W0   = (const float*)d_in[2];
    const float* b0   = (const float*)d_in[3];
    const float* Wc   = (const float*)d_in[4];
    const float* bc   = (const float*)d_in[5];
    const float* Wh   = (const float*)d_in[6];
    const float* bh   = (const float*)d_in[7];
    const float* Wf   = (const float*)d_in[8];
    const float* bf   = (const float*)d_in[9];
    float* out = (float*)d_out;
    const int B = in_sizes[0] / DF;

    prep_w0<<<(NBLK * 2 * 256 * 32 + 255) / 256, 256>>>(W0, Wc, b0, bc);
    prep_wh<<<(NBLK * 2 * 8 * 256 * 32 + 255) / 256, 256>>>(Wh);
    prep_wf<<<(NBLK * NCHK * 8 * FN * 32 + 255) / 256, 256>>>(Wf);
    prep_bh<<<(NBLK * 2 * 256 + 255) / 256, 256>>>(bh);

    cudaFuncSetAttribute(maf_kernel, cudaFuncAttributeMaxDynamicSharedMemorySize, SMEM_BYTES);
    maf_kernel<<<B / MROWS, NTHR, SMEM_BYTES>>>(x, cond, bf, out);
}

// round 13
// speedup vs baseline: 14.1422x; 1.0644x over previous
#include <cuda_runtime.h>
#include <cuda_fp16.h>

// ---------------- problem constants ----------------
#define NBLK 6
#define DF   45
#define DM   1035
#define MROWS 64           // rows per CTA (two independent 32-row groups)
#define NTHR 256

#define Z32S 49            // fp32 z row stride
#define Z16S 72            // fp16 z row stride (halves), 64 cols (2 k-slabs)
#define AS16 264           // fp16 act row stride (halves), 256 cols (8 k-slabs)
#define FN   192           // f-chunk cols (8 features x 24)
#define NCHK 6             // f chunks
#define PSTR 202           // fp16 params row stride (halves) within group sub-block
#define GHALF 16896        // bytes per group half of the region (32*264*2)

// smem byte offsets (total 90368 -> 2 CTAs/SM)
#define OB_Z32  0
#define OB_Z16  12544                 // 64*49*4
#define OB_LDP  (OB_Z16 + 9216)       // [256] fp32
#define OB_ACTA (OB_LDP + 1024)
#define OB_REGN (OB_ACTA + 33792)     // actB [64][264] fp16 ALIASED with per-group par strips
#define SMEM_BYTES (OB_REGN + 33792)  // 90368

// per-N-tile k-slab bounds (degree-sorted hidden): SL[j] nibble-packed
#define SL_PACK 0x88665332u
// per-f-chunk k-slab bounds {2,3,5,6,8,8}
#define FSL_PACK 0x00886532u

#define GBAR(id) asm volatile("bar.sync %0, 128;" :: "r"(id) : "memory")

// ---------------- device weight images (masked, permuted, k-interleaved, LDG-fragment layout) ----------------
__device__ __half g_W0p[NBLK * 2 * 256 * 32];
__device__ __half g_Whp[NBLK * 2 * 8 * 256 * 32];
__device__ __half g_Wfp[NBLK * NCHK * 8 * FN * 32];
__device__ float  g_bhp[NBLK * 2 * 256];     // degree-permuted hidden biases

// ---------------- helpers ----------------
__device__ __forceinline__ void mma16(float* d, unsigned a0, unsigned a1, unsigned a2, unsigned a3,
                                      unsigned b0, unsigned b1) {
    asm volatile("mma.sync.aligned.m16n8k16.row.col.f32.f16.f16.f32 "
        "{%0,%1,%2,%3},{%4,%5,%6,%7},{%8,%9},{%0,%1,%2,%3};"
        : "+f"(d[0]), "+f"(d[1]), "+f"(d[2]), "+f"(d[3])
        : "r"(a0), "r"(a1), "r"(a2), "r"(a3), "r"(b0), "r"(b1));
}
// phys column of logical k within interleaved 32-k slabs (A-side layout)
__device__ __forceinline__ int acol(int c) {
    int s = c >> 5, k32 = c & 31, step = k32 >> 4, w16 = k32 & 15;
    int hi = w16 >> 3, t = (w16 & 7) >> 1, q = hi * 2 + (w16 & 1);
    return s * 32 + t * 8 + step * 4 + q;
}
// logical k from slab s, phys pos p (<32)
__device__ __forceinline__ int kfp2(int s, int p) {
    int t = p >> 3, rem = p & 7, step = rem >> 2, q = rem & 3;
    int w16 = (q < 2) ? (2 * t + q) : (8 + 2 * t + (q - 2));
    return s * 32 + step * 16 + w16;
}
// degree-sort inverse: original hidden unit for sorted index j
__device__ __forceinline__ int invp(int j) {
    return (j < 216) ? (j / 6 + 44 * (j % 6))
                     : (36 + (j - 216) / 5 + 44 * ((j - 216) % 5));
}

// ---------------- prep kernels ----------------
__global__ void prep_w0(const float* __restrict__ W0, const float* __restrict__ Wc,
                        const float* __restrict__ b0, const float* __restrict__ bc) {
    int idx = blockIdx.x * blockDim.x + threadIdx.x;
    if (idx >= NBLK * 2 * 256 * 32) return;
    int p = idx & 31, n = (idx >> 5) & 255, s = (idx >> 13) & 1, b = idx >> 14;
    int k = kfp2(s, p);
    int o = invp(n);
    float v = 0.0f;
    if (k < DF)       v = ((o % 44) >= k) ? W0[(b * 256 + o) * DF + k] : 0.0f;
    else if (k == 45) v = Wc[b * 256 + o];
    else if (k == 46) v = b0[b * 256 + o] + bc[b * 256 + o];
    g_W0p[idx] = __float2half(v);
}
__global__ void prep_wh(const float* __restrict__ Wh) {
    int idx = blockIdx.x * blockDim.x + threadIdx.x;
    if (idx >= NBLK * 2 * 8 * 256 * 32) return;
    int p = idx & 31, n = (idx >> 5) & 255, s = (idx >> 13) & 7, bl = idx >> 16;
    int o = invp(n);
    int kk = invp(kfp2(s, p));
    float v = ((o % 44) >= (kk % 44)) ? Wh[((size_t)(bl * 256 + o)) * 256 + kk] : 0.0f;
    g_Whp[idx] = __float2half(v);
}
__global__ void prep_wf(const float* __restrict__ Wf) {
    int idx = blockIdx.x * blockDim.x + threadIdx.x;
    if (idx >= NBLK * NCHK * 8 * FN * 32) return;
    int p = idx & 31, n = (idx >> 5) % FN, s = (idx / (FN * 32)) & 7;
    int ch = (idx / (FN * 32 * 8)) % NCHK, b = idx / (FN * 32 * 8 * NCHK);
    int kk = invp(kfp2(s, p));
    int fl = n / 24, i = n % 24, f = ch * 8 + fl;
    float v = 0.0f;
    if (i < 23 && f < DF && f > (kk % 44))
        v = Wf[((size_t)(b * DM + f * 23 + i)) * 256 + kk];
    g_Wfp[idx] = __float2half(v);
}
__global__ void prep_bh(const float* __restrict__ bh) {
    int idx = blockIdx.x * blockDim.x + threadIdx.x;
    if (idx >= NBLK * 2 * 256) return;
    int n = idx & 255, bl = idx >> 8;
    g_bhp[idx] = bh[bl * 256 + invp(n)];
}

// ---------------- L0 dense: [64 x 256] = z16[64 x 64] * W0[64 x 256]; group-local ----------------
__device__ __forceinline__ void dense0(const __half* __restrict__ Wg,
                                       const __half* __restrict__ z16,
                                       __half* __restrict__ dst,
                                       int wm, int wn, int lane, int barid)
{
    const int g = lane >> 2, t = lane & 3;

    float acc[2][8][4];
    #pragma unroll
    for (int mt = 0; mt < 2; mt++)
        #pragma unroll
        for (int nt = 0; nt < 8; nt++)
            acc[mt][nt][0] = acc[mt][nt][1] = acc[mt][nt][2] = acc[mt][nt][3] = 0.0f;

    GBAR(barid);   // entry: group's spline z16 writes / group's prior actA readers arrived

    const __half* aprow = z16 + (wm * 32 + g) * Z16S + t * 8;
    const __half* bbase = Wg + ((size_t)(wn * 64 + g)) * 32 + t * 8;

    #pragma unroll
    for (int s = 0; s < 2; s++) {
        uint4 Av[4];
        {
            const __half* ap = aprow + s * 32;
            Av[0] = *(const uint4*)ap;
            Av[1] = *(const uint4*)(ap + 8 * Z16S);
            Av[2] = *(const uint4*)(ap + 16 * Z16S);
            Av[3] = *(const uint4*)(ap + 24 * Z16S);
        }
        const __half* bp = bbase + (size_t)s * (256 * 32);
        #pragma unroll
        for (int nt = 0; nt < 8; nt++) {
            uint4 Bv = *(const uint4*)(bp + nt * (8 * 32));
            mma16(acc[0][nt], Av[0].x, Av[1].x, Av[0].y, Av[1].y, Bv.x, Bv.y);
            mma16(acc[1][nt], Av[2].x, Av[3].x, Av[2].y, Av[3].y, Bv.x, Bv.y);
            mma16(acc[0][nt], Av[0].z, Av[1].z, Av[0].w, Av[1].w, Bv.z, Bv.w);
            mma16(acc[1][nt], Av[2].z, Av[3].z, Av[2].w, Av[3].w, Bv.z, Bv.w);
        }
    }
    #pragma unroll
    for (int nt = 0; nt < 8; nt++) {
        int c0 = wn * 64 + nt * 8 + 2 * t;
        int pos = acol(c0);
        #pragma unroll
        for (int mt = 0; mt < 2; mt++) {
            int r0 = wm * 32 + mt * 16 + g;
            *(half2*)(dst + r0 * AS16 + pos)       = __floats2half2_rn(acc[mt][nt][0], acc[mt][nt][1]);
            *(half2*)(dst + (r0 + 8) * AS16 + pos) = __floats2half2_rn(acc[mt][nt][2], acc[mt][nt][3]);
        }
    }
}

// ---------------- hidden dense (degree-sorted, per-warp truncated K), OUT-OF-PLACE, group-local ----------------
__device__ __forceinline__ void hidden_dense(const __half* __restrict__ Wg,
                                             const float* __restrict__ biasP,
                                             const __half* __restrict__ src,
                                             __half* __restrict__ dst,
                                             int wm, int wj, int lane, int barid)
{
    const int g = lane >> 2, t = lane & 3;

    float acc[2][2][4][4];
    #pragma unroll
    for (int ti = 0; ti < 2; ti++)
        #pragma unroll
        for (int mt = 0; mt < 2; mt++)
            #pragma unroll
            for (int j = 0; j < 4; j++)
                acc[ti][mt][j][0] = acc[ti][mt][j][1] = acc[ti][mt][j][2] = acc[ti][mt][j][3] = 0.0f;

    GBAR(barid);   // entry: group's src writers / group's prior dst readers arrived

    const __half* aprow = src + (wm * 32 + g) * AS16 + t * 8;

    #pragma unroll
    for (int ti = 0; ti < 2; ti++) {
        const int tile = ti ? (7 - wj) : wj;
        const int ns = (int)((SL_PACK >> (4 * tile)) & 0xFu);
        const __half* bbase = Wg + ((size_t)(tile * 32 + g)) * 32 + t * 8;
        for (int s = 0; s < ns; s++) {
            uint4 Av[4];
            {
                const __half* ap = aprow + s * 32;
                Av[0] = *(const uint4*)ap;
                Av[1] = *(const uint4*)(ap + 8 * AS16);
                Av[2] = *(const uint4*)(ap + 16 * AS16);
                Av[3] = *(const uint4*)(ap + 24 * AS16);
            }
            const __half* bp = bbase + (size_t)s * (256 * 32);
            #pragma unroll
            for (int j = 0; j < 4; j++) {
                uint4 Bv = *(const uint4*)(bp + j * (8 * 32));
                mma16(acc[ti][0][j], Av[0].x, Av[1].x, Av[0].y, Av[1].y, Bv.x, Bv.y);
                mma16(acc[ti][1][j], Av[2].x, Av[3].x, Av[2].y, Av[3].y, Bv.x, Bv.y);
                mma16(acc[ti][0][j], Av[0].z, Av[1].z, Av[0].w, Av[1].w, Bv.z, Bv.w);
                mma16(acc[ti][1][j], Av[2].z, Av[3].z, Av[2].w, Av[3].w, Bv.z, Bv.w);
            }
        }
    }
    #pragma unroll
    for (int ti = 0; ti < 2; ti++) {
        const int tile = ti ? (7 - wj) : wj;
        #pragma unroll
        for (int j = 0; j < 4; j++) {
            int c0 = tile * 32 + j * 8 + 2 * t;
            int pos = acol(c0);
            float2 bb = *(const float2*)(biasP + c0);
            #pragma unroll
            for (int mt = 0; mt < 2; mt++) {
                int r0 = wm * 32 + mt * 16 + g;
                float v0 = fmaxf(acc[ti][mt][j][0] + bb.x, 0.0f);
                float v1 = fmaxf(acc[ti][mt][j][1] + bb.y, 0.0f);
                float v2 = fmaxf(acc[ti][mt][j][2] + bb.x, 0.0f);
                float v3 = fmaxf(acc[ti][mt][j][3] + bb.y, 0.0f);
                *(half2*)(dst + r0 * AS16 + pos)       = __floats2half2_rn(v0, v1);
                *(half2*)(dst + (r0 + 8) * AS16 + pos) = __floats2half2_rn(v2, v3);
            }
        }
    }
}

// ---------------- f-layer chunk MMA + epilogue to the warp's PRIVATE par strip (no barrier) ----------------
__device__ __forceinline__ void f_chunk(const __half* __restrict__ Wg,
                                        const __half* __restrict__ act,
                                        __half* __restrict__ parg,   // group par base (rows local 0..31)
                                        int wm, int wn, int lane, int ns)
{
    const int g = lane >> 2, t = lane & 3;

    float acc[2][6][4];
    #pragma unroll
    for (int mt = 0; mt < 2; mt++)
        #pragma unroll
        for (int nt = 0; nt < 6; nt++)
            acc[mt][nt][0] = acc[mt][nt][1] = acc[mt][nt][2] = acc[mt][nt][3] = 0.0f;

    const __half* aprow = act + (wm * 32 + g) * AS16 + t * 8;
    const __half* bbase = Wg + ((size_t)(wn * 48 + g)) * 32 + t * 8;

    for (int s = 0; s < ns; s++) {
        uint4 Av[4];
        {
            const __half* ap = aprow + s * 32;
            Av[0] = *(const uint4*)ap;
            Av[1] = *(const uint4*)(ap + 8 * AS16);
            Av[2] = *(const uint4*)(ap + 16 * AS16);
            Av[3] = *(const uint4*)(ap + 24 * AS16);
        }
        const __half* bp = bbase + (size_t)s * (FN * 32);
        #pragma unroll
        for (int nt = 0; nt < 6; nt++) {
            uint4 Bv = *(const uint4*)(bp + nt * (8 * 32));
            mma16(acc[0][nt], Av[0].x, Av[1].x, Av[0].y, Av[1].y, Bv.x, Bv.y);
            mma16(acc[1][nt], Av[2].x, Av[3].x, Av[2].y, Av[3].y, Bv.x, Bv.y);
            mma16(acc[0][nt], Av[0].z, Av[1].z, Av[0].w, Av[1].w, Bv.z, Bv.w);
            mma16(acc[1][nt], Av[2].z, Av[3].z, Av[2].w, Av[3].w, Bv.z, Bv.w);
        }
    }
    #pragma unroll
    for (int nt = 0; nt < 6; nt++) {
        int c0 = wn * 48 + nt * 8 + 2 * t;
        #pragma unroll
        for (int mt = 0; mt < 2; mt++) {
            int rl = mt * 16 + g;      // group-local row
            *(half2*)(parg + rl * PSTR + c0)       = __floats2half2_rn(acc[mt][nt][0], acc[mt][nt][1]);
            *(half2*)(parg + (rl + 8) * PSTR + c0) = __floats2half2_rn(acc[mt][nt][2], acc[mt][nt][3]);
        }
    }
}

// ---------------- rational-quadratic spline, K=8 bins ----------------
__device__ __forceinline__ float2 rq_spline(const float* __restrict__ p, float x)
{
    const float TAIL = 13.815510557964274f;
    const float INVS = 0.0625f;
    bool inside = (x >= -TAIL) && (x <= TAIL);
    float xc = fminf(fmaxf(x, -TAIL), TAIL);

    float ew[8], eh[8];
    float sw = 0.0f, sh = 0.0f;
    #pragma unroll
    for (int i = 0; i < 8; i++) {
        ew[i] = __expf(p[i] * INVS);      sw += ew[i];
        eh[i] = __expf(p[8 + i] * INVS);  sh += eh[i];
    }
    float iw = 1.0f / sw, ih = 1.0f / sh;

    float d[9]; d[0] = 1.0f; d[8] = 1.0f;
    #pragma unroll
    for (int i = 0; i < 7; i++) {
        float u = p[16 + i];
        d[i + 1] = 1e-3f + fmaxf(u, 0.0f) + log1pf(__expf(-fabsf(u)));
    }

    float cumw = 0.0f, cumh = 0.0f, cwl = -TAIL, chl = -TAIL;
    float bcwl = -TAIL, bw = 1.0f, bchl = -TAIL, bh2 = 1.0f, bd0 = 1.0f, bd1 = 1.0f;
    #pragma unroll
    for (int i = 0; i < 8; i++) {
        cumw += 1e-3f + 0.992f * (ew[i] * iw);
        cumh += 1e-3f + 0.992f * (eh[i] * ih);
        float cwr = (i == 7) ? TAIL : fmaf(2.0f * TAIL, cumw, -TAIL);
        float chr = (i == 7) ? TAIL : fmaf(2.0f * TAIL, cumh, -TAIL);
        if (xc >= cwl) { bcwl = cwl; bw = cwr - cwl; bchl = chl; bh2 = chr - chl; bd0 = d[i]; bd1 = d[i + 1]; }
        cwl = cwr; chl = chr;
    }

    float th  = (xc - bcwl) / bw;
    float th1 = th * (1.0f - th);
    float dl  = bh2 / bw;
    float den = dl + (bd0 + bd1 - 2.0f * dl) * th1;
    float y   = bchl + bh2 * (dl * th * th + bd0 * th1) / den;
    float omt = 1.0f - th;
    float ln  = dl * dl * (bd1 * th * th + 2.0f * dl * th1 + bd0 * omt * omt);
    float lad = __logf(ln) - 2.0f * __logf(den);
    float2 r; r.x = inside ? y : x; r.y = inside ? lad : 0.0f;
    return r;
}

// ---------------- main fused kernel ----------------
__global__ void __launch_bounds__(NTHR, 2)
maf_kernel(const float* __restrict__ x, const float* __restrict__ cond,
           const float* __restrict__ bf,
           float* __restrict__ out)
{
    extern __shared__ char smc[];
    float*  z32  = (float*)(smc + OB_Z32);    // [64][49]
    __half* z16  = (__half*)(smc + OB_Z16);   // [64][72]
    float*  ldp  = (float*)(smc + OB_LDP);    // [256]
    __half* actA = (__half*)(smc + OB_ACTA);  // [64][264]
    __half* actB = (__half*)(smc + OB_REGN);  // [64][264]; per-group halves alias par strips

    const int tid  = threadIdx.x;
    const int lane = tid & 31, w = tid >> 5;
    const int wm = w & 1, wn = w >> 1;        // group wm; within-group warp wn (0..3)
    const int barid = 1 + wm;
    const int gl = wn * 32 + lane;            // group-local thread index 0..127
    const int row0 = blockIdx.x * MROWS;
    __half* parg = (__half*)(smc + OB_REGN + wm * GHALF);   // group par strip (rows local 0..31)
    float ldacc = 0.0f;

    // group-local init (rows wm*32 .. wm*32+31)
    for (int i = gl; i < 32 * DF; i += 128) {
        int rl = i / DF, f = i - rl * DF;
        int r = wm * 32 + rl;
        z32[r * Z32S + f] = x[(row0 + r) * DF + f];
    }
    for (int i = gl; i < 32 * 64; i += 128) {
        int rl = i >> 6, f = i & 63, r = wm * 32 + rl;
        float v = (f < DF) ? x[(row0 + r) * DF + f]
                 : (f == 45) ? cond[row0 + r]
                 : (f == 46) ? 1.0f : 0.0f;
        z16[r * Z16S + acol(f)] = __float2half(v);
    }
    // ordering via dense0 entry group barrier

    for (int b = 0; b < NBLK; b++) {
        dense0(g_W0p + (size_t)b * 2 * 256 * 32, z16, actA, wm, wn, lane, barid);
        hidden_dense(g_Whp + (size_t)(b * 2 + 0) * 8 * 256 * 32, g_bhp + (b * 2 + 0) * 256,
                     actA, actB, wm, wn, lane, barid);
        hidden_dense(g_Whp + (size_t)(b * 2 + 1) * 8 * 256 * 32, g_bhp + (b * 2 + 1) * 256,
                     actB, actA, wm, wn, lane, barid);

        GBAR(barid);   // group: actB reads done (hidden2), actA writes visible -> f-phase may alias actB with par
        const __half* Wfb = g_Wfp + (size_t)(b * NCHK) * 8 * FN * 32;
        for (int ch = 0; ch < NCHK; ch++) {
            int ns = (int)((FSL_PACK >> (4 * ch)) & 0xFu);
            f_chunk(Wfb + (size_t)ch * 8 * FN * 32, actA, parg, wm, wn, lane, ns);
            __syncwarp();        // warp's par strip writes visible to all its lanes
            #pragma unroll
            for (int q = 0; q < 2; q++) {
                int fl = 2 * wn + q;
                int f = ch * 8 + fl;
                if (f < DF) {
                    int r = wm * 32 + lane;
                    float p[23];
                    const float* bfp = bf + b * DM + f * 23;
                    const __half* pp = parg + lane * PSTR + fl * 24;
                    #pragma unroll
                    for (int i = 0; i < 23; i++)
                        p[i] = __half2float(pp[i]) + bfp[i];
                    float xv = z32[r * Z32S + f];
                    float2 yr = rq_spline(p, xv);
                    z32[r * Z32S + f] = yr.x;
                    z16[r * Z16S + acol(f)] = __float2half(yr.x);
                    ldacc += yr.y;
                }
            }
            __syncwarp();        // par strip reads done before next chunk overwrites it
        }
    }

    ldp[tid] = ldacc;
    __syncthreads();
    if (tid < MROWS) {
        int l = tid & 31, wmr = tid >> 5;
        float ld = ldp[(0 * 2 + wmr) * 32 + l] + ldp[(1 * 2 + wmr) * 32 + l]
                 + ldp[(2 * 2 + wmr) * 32 + l] + ldp[(3 * 2 + wmr) * 32 + l];
        float s = 0.0f;
        #pragma unroll
        for (int f = 0; f < DF; f++) { float v = z32[tid * Z32S + f]; s = fmaf(v, v, s); }
        out[row0 + tid] = -0.5f * s - 41.35223399420827f + ld;
    }
}

// ---------------- launch ----------------
extern "C" void kernel_launch(void* const* d_in, const int* in_sizes, int n_in,
                              void* d_out, int out_size) {
    const float* x    = (const float*)d_in[0];
    const float* cond = (const float*)d_in[1];
    const float* W0   = (const float*)d_in[2];
    const float* b0   = (const float*)d_in[3];
    const float* Wc   = (const float*)d_in[4];
    const float* bc   = (const float*)d_in[5];
    const float* Wh   = (const float*)d_in[6];
    const float* bh   = (const float*)d_in[7];
    const float* Wf   = (const float*)d_in[8];
    const float* bf   = (const float*)d_in[9];
    float* out = (float*)d_out;
    const int B = in_sizes[0] / DF;

    prep_w0<<<(NBLK * 2 * 256 * 32 + 255) / 256, 256>>>(W0, Wc, b0, bc);
    prep_wh<<<(NBLK * 2 * 8 * 256 * 32 + 255) / 256, 256>>>(Wh);
    prep_wf<<<(NBLK * NCHK * 8 * FN * 32 + 255) / 256, 256>>>(Wf);
    prep_bh<<<(NBLK * 2 * 256 + 255) / 256, 256>>>(bh);

    cudaFuncSetAttribute(maf_kernel, cudaFuncAttributeMaxDynamicSharedMemorySize, SMEM_BYTES);
    maf_kernel<<<B / MROWS, NTHR, SMEM_BYTES>>>(x, cond, bf, out);
}